// round 1
// baseline (speedup 1.0000x reference)
#include <cuda_runtime.h>
#include <cuda_bf16.h>
#include <math_constants.h>

#define B_  4
#define N_  4096
#define C_  256
#define CK_ 32
#define TQ  64
#define TK  64

// Scratch (allocation-free rule: __device__ globals)
__device__ float g_f[B_ * N_ * CK_];   // keys    [B,N,32]
__device__ float g_g[B_ * N_ * CK_];   // queries [B,N,32]
__device__ float g_h[B_ * N_ * C_];    // values  [B,N,256]

// ---------------------------------------------------------------------------
// Projection GEMM: C[M,Nc] = A[M,K] @ W[K,Nc] + bias.  BM=64, BN=32, BK=32.
// 256 threads; thread = (col 0..31, row-group 0..7) computes 8 outputs.
// ---------------------------------------------------------------------------
__global__ __launch_bounds__(256) void proj_gemm(
    const float* __restrict__ A, const float* __restrict__ W,
    const float* __restrict__ bias, float* __restrict__ C,
    int M, int K, int Nc)
{
    __shared__ float sA[64 * 33];
    __shared__ float sW[32 * 33];
    const int tid  = threadIdx.x;
    const int col  = tid & 31;
    const int rg   = tid >> 5;
    const int row0 = blockIdx.y * 64;
    const int col0 = blockIdx.x * 32;

    float acc[8];
#pragma unroll
    for (int i = 0; i < 8; i++) acc[i] = 0.f;

    for (int k0 = 0; k0 < K; k0 += 32) {
#pragma unroll
        for (int i = 0; i < 8; i++) {
            int idx = tid + i * 256;                       // 0..2047
            sA[(idx >> 5) * 33 + (idx & 31)] =
                A[(long)(row0 + (idx >> 5)) * K + k0 + (idx & 31)];
        }
#pragma unroll
        for (int i = 0; i < 4; i++) {
            int idx = tid + i * 256;                       // 0..1023
            sW[(idx >> 5) * 33 + (idx & 31)] =
                W[(long)(k0 + (idx >> 5)) * Nc + col0 + (idx & 31)];
        }
        __syncthreads();
#pragma unroll 8
        for (int kk = 0; kk < 32; kk++) {
            float w = sW[kk * 33 + col];
#pragma unroll
            for (int i = 0; i < 8; i++)
                acc[i] = fmaf(sA[(rg * 8 + i) * 33 + kk], w, acc[i]);
        }
        __syncthreads();
    }
    float bv = bias[col0 + col];
#pragma unroll
    for (int i = 0; i < 8; i++)
        C[(long)(row0 + rg * 8 + i) * Nc + col0 + col] = acc[i] + bv;
}

// ---------------------------------------------------------------------------
// Flash attention over 4096 keys, fp32, online softmax.
// Block: (query tile of 64 rows) x batch.  256 threads.
// Thread layout: sub = tid&7 owns 32 channels [sub*32, sub*32+32);
//                rp  = tid>>3 owns rows {rp, rp+32} of the tile.
// ---------------------------------------------------------------------------
__global__ __launch_bounds__(256) void attn_kernel(
    const float* __restrict__ fmat, const float* __restrict__ gmat,
    const float* __restrict__ hmat, const float* __restrict__ x,
    const float* __restrict__ gamma, float* __restrict__ y)
{
    extern __shared__ float smem[];
    float*  sg  = smem;                          // 64*33 floats (queries)
    float*  sf  = sg + 64 * 33;                  // 64*33 floats (keys)
    float4* sh4 = (float4*)(sf + 64 * 33);       // 64*64 float4 (values) — 16B aligned
    float*  sS  = (float*)(sh4 + 64 * 64);       // 64*65 floats (scores)

    const int b   = blockIdx.y;
    const int q0  = blockIdx.x * TQ;
    const int tid = threadIdx.x;
    const int sub = tid & 7;
    const int rp  = tid >> 3;

    const float* fp = fmat + (long)b * N_ * CK_;
    const float* gp = gmat + (long)b * N_ * CK_;
    const float* hp = hmat + (long)b * N_ * C_;

    // Load query tile once (contiguous 2048 floats)
#pragma unroll
    for (int i = 0; i < 8; i++) {
        int idx = tid + i * 256;
        sg[(idx >> 5) * 33 + (idx & 31)] = gp[(long)q0 * CK_ + idx];
    }

    float acc0[32], acc1[32];
#pragma unroll
    for (int c = 0; c < 32; c++) { acc0[c] = 0.f; acc1[c] = 0.f; }
    float m0 = -CUDART_INF_F, m1 = -CUDART_INF_F, l0 = 0.f, l1 = 0.f;

    for (int t = 0; t < N_ / TK; t++) {
        __syncthreads();   // protect smem from previous iteration's readers (also covers sg)
        // stage key tile (contiguous 2048 floats)
#pragma unroll
        for (int i = 0; i < 8; i++) {
            int idx = tid + i * 256;
            sf[(idx >> 5) * 33 + (idx & 31)] = fp[(long)t * TK * CK_ + idx];
        }
        // stage value tile (contiguous 4096 float4)
        const float4* h4 = (const float4*)(hp + (long)t * TK * C_);
#pragma unroll
        for (int i = 0; i < 16; i++) {
            int idx = tid + i * 256;
            sh4[idx] = h4[idx];
        }
        __syncthreads();

        // scores: rows {rp, rp+32} x keys [sub*8, sub*8+8)
        float s0[8], s1[8];
#pragma unroll
        for (int i = 0; i < 8; i++) { s0[i] = 0.f; s1[i] = 0.f; }
#pragma unroll 8
        for (int j = 0; j < CK_; j++) {
            float ga = sg[rp * 33 + j];
            float gb = sg[(rp + 32) * 33 + j];
#pragma unroll
            for (int i = 0; i < 8; i++) {
                float fv = sf[(sub * 8 + i) * 33 + j];
                s0[i] = fmaf(ga, fv, s0[i]);
                s1[i] = fmaf(gb, fv, s1[i]);
            }
        }
#pragma unroll
        for (int i = 0; i < 8; i++) {
            sS[rp * 65 + sub * 8 + i]        = s0[i];
            sS[(rp + 32) * 65 + sub * 8 + i] = s1[i];
        }
        __syncthreads();

        // online softmax update for both rows
        float mt0 = -CUDART_INF_F, mt1 = -CUDART_INF_F;
#pragma unroll 8
        for (int k = 0; k < TK; k++) {
            mt0 = fmaxf(mt0, sS[rp * 65 + k]);
            mt1 = fmaxf(mt1, sS[(rp + 32) * 65 + k]);
        }
        float mn0 = fmaxf(m0, mt0), mn1 = fmaxf(m1, mt1);
        float a0 = __expf(m0 - mn0), a1 = __expf(m1 - mn1);
        m0 = mn0; m1 = mn1; l0 *= a0; l1 *= a1;
#pragma unroll
        for (int c = 0; c < 32; c++) { acc0[c] *= a0; acc1[c] *= a1; }

#pragma unroll 2
        for (int k = 0; k < TK; k++) {
            float p0 = __expf(sS[rp * 65 + k] - mn0);
            float p1 = __expf(sS[(rp + 32) * 65 + k] - mn1);
            l0 += p0; l1 += p1;
#pragma unroll
            for (int q = 0; q < 8; q++) {
                float4 hv = sh4[k * 64 + sub * 8 + q];
                acc0[q * 4 + 0] = fmaf(p0, hv.x, acc0[q * 4 + 0]);
                acc0[q * 4 + 1] = fmaf(p0, hv.y, acc0[q * 4 + 1]);
                acc0[q * 4 + 2] = fmaf(p0, hv.z, acc0[q * 4 + 2]);
                acc0[q * 4 + 3] = fmaf(p0, hv.w, acc0[q * 4 + 3]);
                acc1[q * 4 + 0] = fmaf(p1, hv.x, acc1[q * 4 + 0]);
                acc1[q * 4 + 1] = fmaf(p1, hv.y, acc1[q * 4 + 1]);
                acc1[q * 4 + 2] = fmaf(p1, hv.z, acc1[q * 4 + 2]);
                acc1[q * 4 + 3] = fmaf(p1, hv.w, acc1[q * 4 + 3]);
            }
        }
    }

    // epilogue: y = gamma * (acc / l) + x
    float inv0 = 1.f / l0, inv1 = 1.f / l1;
    float gam = gamma[0];
    long r0g = (long)b * N_ + q0 + rp;
    long r1g = r0g + 32;
    const float4* x4 = (const float4*)x;
    float4* y4 = (float4*)y;
#pragma unroll
    for (int q = 0; q < 8; q++) {
        int c4 = sub * 8 + q;
        float4 xv = x4[r0g * 64 + c4];
        float4 ov;
        ov.x = fmaf(gam, acc0[q * 4 + 0] * inv0, xv.x);
        ov.y = fmaf(gam, acc0[q * 4 + 1] * inv0, xv.y);
        ov.z = fmaf(gam, acc0[q * 4 + 2] * inv0, xv.z);
        ov.w = fmaf(gam, acc0[q * 4 + 3] * inv0, xv.w);
        y4[r0g * 64 + c4] = ov;

        xv = x4[r1g * 64 + c4];
        ov.x = fmaf(gam, acc1[q * 4 + 0] * inv1, xv.x);
        ov.y = fmaf(gam, acc1[q * 4 + 1] * inv1, xv.y);
        ov.z = fmaf(gam, acc1[q * 4 + 2] * inv1, xv.z);
        ov.w = fmaf(gam, acc1[q * 4 + 3] * inv1, xv.w);
        y4[r1g * 64 + c4] = ov;
    }
}

// ---------------------------------------------------------------------------
extern "C" void kernel_launch(void* const* d_in, const int* in_sizes, int n_in,
                              void* d_out, int out_size)
{
    const float* x     = (const float*)d_in[0];
    const float* Wf    = (const float*)d_in[1];
    const float* bf    = (const float*)d_in[2];
    const float* Wg    = (const float*)d_in[3];
    const float* bg    = (const float*)d_in[4];
    const float* Wh    = (const float*)d_in[5];
    const float* bh    = (const float*)d_in[6];
    const float* gamma = (const float*)d_in[7];
    float* y = (float*)d_out;

    float *fp, *gp, *hp;
    cudaGetSymbolAddress((void**)&fp, g_f);
    cudaGetSymbolAddress((void**)&gp, g_g);
    cudaGetSymbolAddress((void**)&hp, g_h);

    const int M = B_ * N_;  // 16384 pixels

    proj_gemm<<<dim3(CK_ / 32, M / 64), 256>>>(x, Wf, bf, fp, M, C_, CK_);
    proj_gemm<<<dim3(CK_ / 32, M / 64), 256>>>(x, Wg, bg, gp, M, C_, CK_);
    proj_gemm<<<dim3(C_  / 32, M / 64), 256>>>(x, Wh, bh, hp, M, C_, C_);

    size_t smem_bytes = (size_t)(64 * 33 * 2) * sizeof(float)   // sg + sf
                      + (size_t)(64 * 64) * sizeof(float4)      // sh4
                      + (size_t)(64 * 65) * sizeof(float);      // sS
    cudaFuncSetAttribute(attn_kernel,
                         cudaFuncAttributeMaxDynamicSharedMemorySize,
                         (int)smem_bytes);
    attn_kernel<<<dim3(N_ / TQ, B_), 256, smem_bytes>>>(fp, gp, hp, x, gamma, y);
}

// round 3
// speedup vs baseline: 15.9813x; 15.9813x over previous
#include <cuda_runtime.h>
#include <cuda_bf16.h>
#include <math_constants.h>
#include <cstdint>

#define B_  4
#define N_  4096
#define C_  256
#define CK_ 32

// ---------------------------------------------------------------------------
// Scratch (__device__ globals; allocation-free rule)
// ---------------------------------------------------------------------------
__device__ __align__(16) float g_f[B_ * N_ * CK_];   // keys    fp32 [B,N,32]
__device__ __align__(16) float g_g[B_ * N_ * CK_];   // queries fp32 [B,N,32]
__device__ __align__(16) float g_h[B_ * N_ * C_];    // values  fp32 [B,N,256]
__device__ uint4 g_ht_hi[B_ * C_ * N_ / 8];          // H^T bf16 hi [B,C,N]
__device__ uint4 g_ht_lo[B_ * C_ * N_ / 8];          // H^T bf16 lo [B,C,N]

// ---------------------------------------------------------------------------
// Warp-level MMA helpers (family-portable PTX: sm_80+, legal on sm_103)
// ---------------------------------------------------------------------------
__device__ __forceinline__ uint32_t smem_u32(const void* p) {
    uint32_t a;
    asm("{ .reg .u64 t; cvta.to.shared.u64 t, %1; cvt.u32.u64 %0, t; }" : "=r"(a) : "l"(p));
    return a;
}
__device__ __forceinline__ void ldsm4(uint32_t* r, uint32_t addr) {
    asm volatile("ldmatrix.sync.aligned.m8n8.x4.shared.b16 {%0,%1,%2,%3}, [%4];"
        : "=r"(r[0]), "=r"(r[1]), "=r"(r[2]), "=r"(r[3]) : "r"(addr));
}
__device__ __forceinline__ void mma_bf16(float* d, const uint32_t* a, uint32_t b0, uint32_t b1) {
    asm volatile("mma.sync.aligned.m16n8k16.row.col.f32.bf16.bf16.f32 "
        "{%0,%1,%2,%3}, {%4,%5,%6,%7}, {%8,%9}, {%0,%1,%2,%3};"
        : "+f"(d[0]), "+f"(d[1]), "+f"(d[2]), "+f"(d[3])
        : "r"(a[0]), "r"(a[1]), "r"(a[2]), "r"(a[3]), "r"(b0), "r"(b1));
}

// ---------------------------------------------------------------------------
// Projection GEMM fp32: C[M,Nc] = A[M,K] @ W[K,Nc] + bias
// ---------------------------------------------------------------------------
__global__ __launch_bounds__(256) void proj_gemm(
    const float* __restrict__ A, const float* __restrict__ W,
    const float* __restrict__ bias, float* __restrict__ C,
    int M, int K, int Nc)
{
    __shared__ float sA[64 * 33];
    __shared__ float sW[32 * 33];
    const int tid = threadIdx.x, col = tid & 31, rg = tid >> 5;
    const int row0 = blockIdx.y * 64, col0 = blockIdx.x * 32;
    float acc[8];
#pragma unroll
    for (int i = 0; i < 8; i++) acc[i] = 0.f;
    for (int k0 = 0; k0 < K; k0 += 32) {
#pragma unroll
        for (int i = 0; i < 8; i++) {
            int idx = tid + i * 256;
            sA[(idx >> 5) * 33 + (idx & 31)] = A[(long)(row0 + (idx >> 5)) * K + k0 + (idx & 31)];
        }
#pragma unroll
        for (int i = 0; i < 4; i++) {
            int idx = tid + i * 256;
            sW[(idx >> 5) * 33 + (idx & 31)] = W[(long)(k0 + (idx >> 5)) * Nc + col0 + (idx & 31)];
        }
        __syncthreads();
#pragma unroll 8
        for (int kk = 0; kk < 32; kk++) {
            float w = sW[kk * 33 + col];
#pragma unroll
            for (int i = 0; i < 8; i++)
                acc[i] = fmaf(sA[(rg * 8 + i) * 33 + kk], w, acc[i]);
        }
        __syncthreads();
    }
    float bv = bias[col0 + col];
#pragma unroll
    for (int i = 0; i < 8; i++)
        C[(long)(row0 + rg * 8 + i) * Nc + col0 + col] = acc[i] + bv;
}

// ---------------------------------------------------------------------------
// Transpose h [B,N,C] fp32 -> Ht hi/lo bf16 [B,C,N]
// ---------------------------------------------------------------------------
__global__ __launch_bounds__(256) void transpose_split(
    const float* __restrict__ h, __nv_bfloat16* __restrict__ hi, __nv_bfloat16* __restrict__ lo)
{
    __shared__ float ts[32][33];
    const int b = blockIdx.z, n0 = blockIdx.x * 32, c0 = blockIdx.y * 32;
    const int tx = threadIdx.x & 31, ty = threadIdx.x >> 5;  // 32 x 8
#pragma unroll
    for (int i = 0; i < 4; i++)
        ts[ty + 8 * i][tx] = h[(long)b * N_ * C_ + (long)(n0 + ty + 8 * i) * C_ + c0 + tx];
    __syncthreads();
#pragma unroll
    for (int i = 0; i < 4; i++) {
        int cl = ty + 8 * i;
        float v = ts[tx][cl];
        __nv_bfloat16 hv = __float2bfloat16_rn(v);
        __nv_bfloat16 lv = __float2bfloat16_rn(v - __bfloat162float(hv));
        long idx = (long)b * C_ * N_ + (long)(c0 + cl) * N_ + n0 + tx;
        hi[idx] = hv;
        lo[idx] = lv;
    }
}

// ---------------------------------------------------------------------------
// Attention: block = 64 q-rows x batch. 8 warps = 4(m16) x 2(channel half).
// Fixed-offset softmax p=exp(s-40); O accumulates in regs across all tiles.
// bf16 hi/lo 3-term splits for both GEMMs.
// SMEM layout (XOR-swizzled 16B chunks, 128B rows):
//   sG  [64 q ][32hi|32lo bf16]   @ 0      (8 KB)
//   sF  [64 key][32hi|32lo bf16]  @ 8192   (8 KB)
//   sHhi[256 ch][64 key bf16]     @ 16384  (32 KB)
//   sHlo[256 ch][64 key bf16]     @ 49152  (32 KB)
// ---------------------------------------------------------------------------
#define OFF_SG   0
#define OFF_SF   8192
#define OFF_HHI  16384
#define OFF_HLO  49152
#define SMEM_TOTAL 81920

__global__ __launch_bounds__(256, 1) void attn_mma(
    const float* __restrict__ fmat, const float* __restrict__ gmat,
    const uint4* __restrict__ hhi4, const uint4* __restrict__ htlo4,
    const float* __restrict__ x, const float* __restrict__ gamma, float* __restrict__ y)
{
    extern __shared__ char smem[];
    const uint32_t sb = smem_u32(smem);
    const int tid = threadIdx.x, lane = tid & 31, wid = tid >> 5;
    const int wm = wid & 3, wn = wid >> 2;
    const int b = blockIdx.y, q0 = blockIdx.x * 64;

    // per-thread ldmatrix row/chunk patterns
    const int la_row = (((lane >> 3) & 1) << 3) | (lane & 7);  // A: g0 m0-7,g1 m8-15,g2 m0-7,g3 m8-15
    const int la_sel = lane >> 4;                              //    g0,g1 k-chunk 0; g2,g3 k-chunk 1
    const int lb_row = ((lane >> 4) << 3) | (lane & 7);        // B: g0,g1 n0-7; g2,g3 n8-15
    const int lb_sel = (lane >> 3) & 1;                        //    g0 k0,g1 k1,g2 k0,g3 k1

    // ---- stage G tile (hi|lo bf16) ----
    {
        const int r = tid >> 2, kg = tid & 3;
        const float4* src = (const float4*)(gmat + ((long)b * N_ + q0 + r) * CK_ + kg * 8);
        float4 v0 = src[0], v1 = src[1];
        __nv_bfloat162 h0 = __floats2bfloat162_rn(v0.x, v0.y);
        __nv_bfloat162 h1 = __floats2bfloat162_rn(v0.z, v0.w);
        __nv_bfloat162 h2 = __floats2bfloat162_rn(v1.x, v1.y);
        __nv_bfloat162 h3 = __floats2bfloat162_rn(v1.z, v1.w);
        float2 f0 = __bfloat1622float2(h0), f1 = __bfloat1622float2(h1);
        float2 f2 = __bfloat1622float2(h2), f3 = __bfloat1622float2(h3);
        __nv_bfloat162 l0b = __floats2bfloat162_rn(v0.x - f0.x, v0.y - f0.y);
        __nv_bfloat162 l1b = __floats2bfloat162_rn(v0.z - f1.x, v0.w - f1.y);
        __nv_bfloat162 l2b = __floats2bfloat162_rn(v1.x - f2.x, v1.y - f2.y);
        __nv_bfloat162 l3b = __floats2bfloat162_rn(v1.z - f3.x, v1.w - f3.y);
        uint4 hv = { *(uint32_t*)&h0, *(uint32_t*)&h1, *(uint32_t*)&h2, *(uint32_t*)&h3 };
        uint4 lv = { *(uint32_t*)&l0b, *(uint32_t*)&l1b, *(uint32_t*)&l2b, *(uint32_t*)&l3b };
        *(uint4*)(smem + OFF_SG + r * 128 + (((kg) ^ (r & 7)) << 4)) = hv;
        *(uint4*)(smem + OFF_SG + r * 128 + (((4 + kg) ^ (r & 7)) << 4)) = lv;
    }
    __syncthreads();

    // ---- persistent G A-fragments (hi/lo, k-chunks 0..1) ----
    uint32_t gh[2][4], gl[2][4];
    {
        int row = wm * 16 + la_row;
        uint32_t rowoff = sb + OFF_SG + row * 128;
#pragma unroll
        for (int kc = 0; kc < 2; kc++) {
            ldsm4(gh[kc], rowoff + ((((2 * kc) + la_sel) ^ (row & 7)) << 4));
            ldsm4(gl[kc], rowoff + ((((4 + 2 * kc) + la_sel) ^ (row & 7)) << 4));
        }
    }

    float o[16][4];
#pragma unroll
    for (int i = 0; i < 16; i++)
#pragma unroll
        for (int j = 0; j < 4; j++) o[i][j] = 0.f;
    float lsum0 = 0.f, lsum1 = 0.f;

    const int fr = tid >> 2, fkg = tid & 3;       // F staging pattern
    const long fbase = (long)b * N_ * CK_;
    const long hbase = (long)b * 256 * 512;       // uint4 units

#pragma unroll 1
    for (int t = 0; t < N_ / 64; t++) {
        __syncthreads();
        // ---- stage F tile ----
        {
            const float4* src = (const float4*)(fmat + fbase + ((long)(t * 64 + fr)) * CK_ + fkg * 8);
            float4 v0 = src[0], v1 = src[1];
            __nv_bfloat162 h0 = __floats2bfloat162_rn(v0.x, v0.y);
            __nv_bfloat162 h1 = __floats2bfloat162_rn(v0.z, v0.w);
            __nv_bfloat162 h2 = __floats2bfloat162_rn(v1.x, v1.y);
            __nv_bfloat162 h3 = __floats2bfloat162_rn(v1.z, v1.w);
            float2 f0 = __bfloat1622float2(h0), f1 = __bfloat1622float2(h1);
            float2 f2 = __bfloat1622float2(h2), f3 = __bfloat1622float2(h3);
            __nv_bfloat162 l0b = __floats2bfloat162_rn(v0.x - f0.x, v0.y - f0.y);
            __nv_bfloat162 l1b = __floats2bfloat162_rn(v0.z - f1.x, v0.w - f1.y);
            __nv_bfloat162 l2b = __floats2bfloat162_rn(v1.x - f2.x, v1.y - f2.y);
            __nv_bfloat162 l3b = __floats2bfloat162_rn(v1.z - f3.x, v1.w - f3.y);
            uint4 hv = { *(uint32_t*)&h0, *(uint32_t*)&h1, *(uint32_t*)&h2, *(uint32_t*)&h3 };
            uint4 lv = { *(uint32_t*)&l0b, *(uint32_t*)&l1b, *(uint32_t*)&l2b, *(uint32_t*)&l3b };
            *(uint4*)(smem + OFF_SF + fr * 128 + (((fkg) ^ (fr & 7)) << 4)) = hv;
            *(uint4*)(smem + OFF_SF + fr * 128 + (((4 + fkg) ^ (fr & 7)) << 4)) = lv;
        }
        // ---- stage H^T hi/lo tiles [256 ch][64 keys] ----
#pragma unroll
        for (int i = 0; i < 8; i++) {
            int idx = tid + i * 256;
            int r = idx >> 3, c8 = idx & 7;
            long gi = hbase + (long)r * 512 + t * 8 + c8;
            uint32_t doff = r * 128 + (((c8) ^ (r & 7)) << 4);
            *(uint4*)(smem + OFF_HHI + doff) = hhi4[gi];
            *(uint4*)(smem + OFF_HLO + doff) = htlo4[gi];
        }
        __syncthreads();

        // ---- MMA1: S[16x64] = Gh.Fh + Gh.Fl + Gl.Fh ----
        float s[8][4];
#pragma unroll
        for (int i = 0; i < 8; i++)
#pragma unroll
            for (int j = 0; j < 4; j++) s[i][j] = 0.f;

#pragma unroll
        for (int n16 = 0; n16 < 4; n16++) {
            int row = n16 * 16 + lb_row;
            uint32_t rowoff = sb + OFF_SF + row * 128;
            uint32_t fh0[4], fh1[4], fl0[4], fl1[4];
            ldsm4(fh0, rowoff + (((0 + lb_sel) ^ (row & 7)) << 4));
            ldsm4(fh1, rowoff + (((2 + lb_sel) ^ (row & 7)) << 4));
            ldsm4(fl0, rowoff + (((4 + lb_sel) ^ (row & 7)) << 4));
            ldsm4(fl1, rowoff + (((6 + lb_sel) ^ (row & 7)) << 4));
#pragma unroll
            for (int j = 0; j < 2; j++) {
                float* sd = s[n16 * 2 + j];
                mma_bf16(sd, gh[0], fh0[2 * j], fh0[2 * j + 1]);
                mma_bf16(sd, gh[1], fh1[2 * j], fh1[2 * j + 1]);
                mma_bf16(sd, gh[0], fl0[2 * j], fl0[2 * j + 1]);
                mma_bf16(sd, gh[1], fl1[2 * j], fl1[2 * j + 1]);
                mma_bf16(sd, gl[0], fh0[2 * j], fh0[2 * j + 1]);
                mma_bf16(sd, gl[1], fh1[2 * j], fh1[2 * j + 1]);
            }
        }

        // ---- p = exp(s-40); pack A-frags (hi/lo) in registers ----
        uint32_t phi[16], plo[16];
#pragma unroll
        for (int kc = 0; kc < 4; kc++) {
#pragma unroll
            for (int half = 0; half < 2; half++) {
                float* sd = s[2 * kc + half];
                float p0 = __expf(sd[0] - 40.f);
                float p1 = __expf(sd[1] - 40.f);
                float p2 = __expf(sd[2] - 40.f);
                float p3 = __expf(sd[3] - 40.f);
                lsum0 += p0 + p1;
                lsum1 += p2 + p3;
                __nv_bfloat162 h01 = __floats2bfloat162_rn(p0, p1);
                __nv_bfloat162 h23 = __floats2bfloat162_rn(p2, p3);
                float2 f01 = __bfloat1622float2(h01);
                float2 f23 = __bfloat1622float2(h23);
                __nv_bfloat162 q01 = __floats2bfloat162_rn(p0 - f01.x, p1 - f01.y);
                __nv_bfloat162 q23 = __floats2bfloat162_rn(p2 - f23.x, p3 - f23.y);
                phi[kc * 4 + half * 2 + 0] = *(uint32_t*)&h01;
                phi[kc * 4 + half * 2 + 1] = *(uint32_t*)&h23;
                plo[kc * 4 + half * 2 + 0] = *(uint32_t*)&q01;
                plo[kc * 4 + half * 2 + 1] = *(uint32_t*)&q23;
            }
        }

        // ---- MMA2: O[16x128] += Ph.Hh + Ph.Hl + Pl.Hh ----
#pragma unroll
        for (int n16 = 0; n16 < 8; n16++) {
            int row = wn * 128 + n16 * 16 + lb_row;
            uint32_t rhioff = sb + OFF_HHI + row * 128;
            uint32_t rlooff = sb + OFF_HLO + row * 128;
#pragma unroll
            for (int kc = 0; kc < 4; kc++) {
                uint32_t bh[4], bl[4];
                uint32_t csel = (((2 * kc) + lb_sel) ^ (row & 7)) << 4;
                ldsm4(bh, rhioff + csel);
                ldsm4(bl, rlooff + csel);
#pragma unroll
                for (int j = 0; j < 2; j++) {
                    float* od = o[n16 * 2 + j];
                    mma_bf16(od, &phi[kc * 4], bh[2 * j], bh[2 * j + 1]);
                    mma_bf16(od, &phi[kc * 4], bl[2 * j], bl[2 * j + 1]);
                    mma_bf16(od, &plo[kc * 4], bh[2 * j], bh[2 * j + 1]);
                }
            }
        }
    }

    // ---- reduce l over the 4 lanes sharing a row ----
    lsum0 += __shfl_xor_sync(0xFFFFFFFFu, lsum0, 1);
    lsum0 += __shfl_xor_sync(0xFFFFFFFFu, lsum0, 2);
    lsum1 += __shfl_xor_sync(0xFFFFFFFFu, lsum1, 1);
    lsum1 += __shfl_xor_sync(0xFFFFFFFFu, lsum1, 2);
    const float inv0 = 1.f / lsum0, inv1 = 1.f / lsum1;
    const float gam = gamma[0];

    // ---- epilogue: y = gamma * O/l + x ----
    const long row0g = ((long)b * N_ + q0 + wm * 16 + (lane >> 2)) * C_;
    const long row1g = row0g + 8 * C_;
#pragma unroll
    for (int n16 = 0; n16 < 8; n16++) {
#pragma unroll
        for (int j = 0; j < 2; j++) {
            const float* od = o[n16 * 2 + j];
            int ch = wn * 128 + n16 * 16 + j * 8 + (lane & 3) * 2;
            float2 xv = *(const float2*)(x + row0g + ch);
            float2 yv;
            yv.x = fmaf(gam, od[0] * inv0, xv.x);
            yv.y = fmaf(gam, od[1] * inv0, xv.y);
            *(float2*)(y + row0g + ch) = yv;
            xv = *(const float2*)(x + row1g + ch);
            yv.x = fmaf(gam, od[2] * inv1, xv.x);
            yv.y = fmaf(gam, od[3] * inv1, xv.y);
            *(float2*)(y + row1g + ch) = yv;
        }
    }
}

// ---------------------------------------------------------------------------
extern "C" void kernel_launch(void* const* d_in, const int* in_sizes, int n_in,
                              void* d_out, int out_size)
{
    const float* x     = (const float*)d_in[0];
    const float* Wf    = (const float*)d_in[1];
    const float* bf    = (const float*)d_in[2];
    const float* Wg    = (const float*)d_in[3];
    const float* bg    = (const float*)d_in[4];
    const float* Wh    = (const float*)d_in[5];
    const float* bh    = (const float*)d_in[6];
    const float* gamma = (const float*)d_in[7];
    float* y = (float*)d_out;

    float *fp, *gp, *hp;
    void *hthi, *htlo;
    cudaGetSymbolAddress((void**)&fp, g_f);
    cudaGetSymbolAddress((void**)&gp, g_g);
    cudaGetSymbolAddress((void**)&hp, g_h);
    cudaGetSymbolAddress(&hthi, g_ht_hi);
    cudaGetSymbolAddress(&htlo, g_ht_lo);

    const int M = B_ * N_;

    proj_gemm<<<dim3(1, M / 64), 256>>>(x, Wf, bf, fp, M, C_, CK_);
    proj_gemm<<<dim3(1, M / 64), 256>>>(x, Wg, bg, gp, M, C_, CK_);
    proj_gemm<<<dim3(C_ / 32, M / 64), 256>>>(x, Wh, bh, hp, M, C_, C_);
    transpose_split<<<dim3(N_ / 32, C_ / 32, B_), 256>>>(
        hp, (__nv_bfloat16*)hthi, (__nv_bfloat16*)htlo);

    cudaFuncSetAttribute(attn_mma, cudaFuncAttributeMaxDynamicSharedMemorySize, SMEM_TOTAL);
    attn_mma<<<dim3(N_ / 64, B_), 256, SMEM_TOTAL>>>(
        fp, gp, (const uint4*)hthi, (const uint4*)htlo, x, gamma, y);
}

// round 4
// speedup vs baseline: 18.3203x; 1.1464x over previous
#include <cuda_runtime.h>
#include <cuda_bf16.h>
#include <math_constants.h>
#include <cstdint>

#define B_  4
#define N_  4096
#define C_  256
#define CK_ 32
#define NT_ 64   // key tiles of 64

// ---------------------------------------------------------------------------
// Scratch (__device__ globals; allocation-free rule)
// ---------------------------------------------------------------------------
__device__ __align__(16) float g_h[B_ * N_ * C_];        // values fp32 [B,N,256]
__device__ uint4 g_fs[B_ * N_ * 8];                      // F split bf16 [B,N,(32hi|32lo)]
__device__ uint4 g_gs[B_ * N_ * 8];                      // G split bf16 [B,N,(32hi|32lo)]
__device__ uint4 g_ht_hi[B_ * C_ * N_ / 8];              // H^T bf16 hi [B,C,N]
__device__ uint4 g_ht_lo[B_ * C_ * N_ / 8];              // H^T bf16 lo [B,C,N]

// ---------------------------------------------------------------------------
// Helpers
// ---------------------------------------------------------------------------
__device__ __forceinline__ uint32_t smem_u32(const void* p) {
    uint32_t a;
    asm("{ .reg .u64 t; cvta.to.shared.u64 t, %1; cvt.u32.u64 %0, t; }" : "=r"(a) : "l"(p));
    return a;
}
__device__ __forceinline__ void ldsm4(uint32_t* r, uint32_t addr) {
    asm volatile("ldmatrix.sync.aligned.m8n8.x4.shared.b16 {%0,%1,%2,%3}, [%4];"
        : "=r"(r[0]), "=r"(r[1]), "=r"(r[2]), "=r"(r[3]) : "r"(addr));
}
__device__ __forceinline__ void mma_bf16(float* d, const uint32_t* a, uint32_t b0, uint32_t b1) {
    asm volatile("mma.sync.aligned.m16n8k16.row.col.f32.bf16.bf16.f32 "
        "{%0,%1,%2,%3}, {%4,%5,%6,%7}, {%8,%9}, {%0,%1,%2,%3};"
        : "+f"(d[0]), "+f"(d[1]), "+f"(d[2]), "+f"(d[3])
        : "r"(a[0]), "r"(a[1]), "r"(a[2]), "r"(a[3]), "r"(b0), "r"(b1));
}
__device__ __forceinline__ void cp16(uint32_t dst, const void* src) {
    asm volatile("cp.async.cg.shared.global [%0], [%1], 16;" :: "r"(dst), "l"(src) : "memory");
}
#define CP_COMMIT()  asm volatile("cp.async.commit_group;" ::: "memory")
#define CP_WAIT(n)   asm volatile("cp.async.wait_group %0;" :: "n"(n) : "memory")

// ---------------------------------------------------------------------------
// Projection GEMM fp32 (for h): C[M,Nc] = A[M,K] @ W[K,Nc] + bias
// ---------------------------------------------------------------------------
__global__ __launch_bounds__(256) void proj_gemm(
    const float* __restrict__ A, const float* __restrict__ W,
    const float* __restrict__ bias, float* __restrict__ C,
    int M, int K, int Nc)
{
    __shared__ float sA[64 * 33];
    __shared__ float sW[32 * 33];
    const int tid = threadIdx.x, col = tid & 31, rg = tid >> 5;
    const int row0 = blockIdx.y * 64, col0 = blockIdx.x * 32;
    float acc[8];
#pragma unroll
    for (int i = 0; i < 8; i++) acc[i] = 0.f;
    for (int k0 = 0; k0 < K; k0 += 32) {
#pragma unroll
        for (int i = 0; i < 8; i++) {
            int idx = tid + i * 256;
            sA[(idx >> 5) * 33 + (idx & 31)] = A[(long)(row0 + (idx >> 5)) * K + k0 + (idx & 31)];
        }
#pragma unroll
        for (int i = 0; i < 4; i++) {
            int idx = tid + i * 256;
            sW[(idx >> 5) * 33 + (idx & 31)] = W[(long)(k0 + (idx >> 5)) * Nc + col0 + (idx & 31)];
        }
        __syncthreads();
#pragma unroll 8
        for (int kk = 0; kk < 32; kk++) {
            float w = sW[kk * 33 + col];
#pragma unroll
            for (int i = 0; i < 8; i++)
                acc[i] = fmaf(sA[(rg * 8 + i) * 33 + kk], w, acc[i]);
        }
        __syncthreads();
    }
    float bv = bias[col0 + col];
#pragma unroll
    for (int i = 0; i < 8; i++)
        C[(long)(row0 + rg * 8 + i) * Nc + col0 + col] = acc[i] + bv;
}

// ---------------------------------------------------------------------------
// Projection GEMM fp32 -> split bf16 hi/lo output [M][(32hi|32lo)] (for f, g)
// Nc is fixed 32 (one column tile).
// ---------------------------------------------------------------------------
__global__ __launch_bounds__(256) void proj_gemm_split(
    const float* __restrict__ A, const float* __restrict__ W,
    const float* __restrict__ bias, __nv_bfloat16* __restrict__ out,
    int M, int K)
{
    __shared__ float sA[64 * 33];
    __shared__ float sW[32 * 33];
    const int tid = threadIdx.x, col = tid & 31, rg = tid >> 5;
    const int row0 = blockIdx.y * 64;
    float acc[8];
#pragma unroll
    for (int i = 0; i < 8; i++) acc[i] = 0.f;
    for (int k0 = 0; k0 < K; k0 += 32) {
#pragma unroll
        for (int i = 0; i < 8; i++) {
            int idx = tid + i * 256;
            sA[(idx >> 5) * 33 + (idx & 31)] = A[(long)(row0 + (idx >> 5)) * K + k0 + (idx & 31)];
        }
#pragma unroll
        for (int i = 0; i < 4; i++) {
            int idx = tid + i * 256;
            sW[(idx >> 5) * 33 + (idx & 31)] = W[(long)(k0 + (idx >> 5)) * 32 + (idx & 31)];
        }
        __syncthreads();
#pragma unroll 8
        for (int kk = 0; kk < 32; kk++) {
            float w = sW[kk * 33 + col];
#pragma unroll
            for (int i = 0; i < 8; i++)
                acc[i] = fmaf(sA[(rg * 8 + i) * 33 + kk], w, acc[i]);
        }
        __syncthreads();
    }
    float bv = bias[col];
#pragma unroll
    for (int i = 0; i < 8; i++) {
        float v = acc[i] + bv;
        __nv_bfloat16 hv = __float2bfloat16_rn(v);
        __nv_bfloat16 lv = __float2bfloat16_rn(v - __bfloat162float(hv));
        long r = row0 + rg * 8 + i;
        out[r * 64 + col] = hv;
        out[r * 64 + 32 + col] = lv;
    }
}

// ---------------------------------------------------------------------------
// Transpose h [B,N,C] fp32 -> Ht hi/lo bf16 [B,C,N]
// ---------------------------------------------------------------------------
__global__ __launch_bounds__(256) void transpose_split(
    const float* __restrict__ h, __nv_bfloat16* __restrict__ hi, __nv_bfloat16* __restrict__ lo)
{
    __shared__ float ts[32][33];
    const int b = blockIdx.z, n0 = blockIdx.x * 32, c0 = blockIdx.y * 32;
    const int tx = threadIdx.x & 31, ty = threadIdx.x >> 5;
#pragma unroll
    for (int i = 0; i < 4; i++)
        ts[ty + 8 * i][tx] = h[(long)b * N_ * C_ + (long)(n0 + ty + 8 * i) * C_ + c0 + tx];
    __syncthreads();
#pragma unroll
    for (int i = 0; i < 4; i++) {
        int cl = ty + 8 * i;
        float v = ts[tx][cl];
        __nv_bfloat16 hv = __float2bfloat16_rn(v);
        __nv_bfloat16 lv = __float2bfloat16_rn(v - __bfloat162float(hv));
        long idx = (long)b * C_ * N_ + (long)(c0 + cl) * N_ + n0 + tx;
        hi[idx] = hv;
        lo[idx] = lv;
    }
}

// ---------------------------------------------------------------------------
// Attention: block = 128 q-rows x batch (grid 32x4 = 128 blocks, 1/SM).
// 8 warps: wm = wid&3 (32 q-rows each, as 2x m16), wn = wid>>2 (128 ch each).
// cp.async 2-stage pipeline for F (8KB) + Hhi/Hlo (64KB) tiles.
// Fixed-offset softmax p=exp(s-40); O in regs across all 64 key tiles.
// ---------------------------------------------------------------------------
#define OFF_SG     0                       // 128 x 128B = 16 KB
#define STAGE_SZ   (8192 + 65536)          // F + Hhi+Hlo = 72 KB
#define OFF_SF(s)  (16384 + (s) * STAGE_SZ)
#define OFF_HHI(s) (16384 + (s) * STAGE_SZ + 8192)
#define OFF_HLO(s) (16384 + (s) * STAGE_SZ + 8192 + 32768)
#define SMEM_TOTAL (16384 + 2 * STAGE_SZ)  // 160 KB

__global__ __launch_bounds__(256, 1) void attn_mma(
    const uint4* __restrict__ fsplit, const uint4* __restrict__ gsplit,
    const uint4* __restrict__ hhi4, const uint4* __restrict__ hlo4,
    const float* __restrict__ x, const float* __restrict__ gamma, float* __restrict__ y)
{
    extern __shared__ char smem[];
    const uint32_t sb = smem_u32(smem);
    const int tid = threadIdx.x, lane = tid & 31, wid = tid >> 5;
    const int wm = wid & 3, wn = wid >> 2;
    const int b = blockIdx.y, q0 = blockIdx.x * 128;

    const int la_row = (((lane >> 3) & 1) << 3) | (lane & 7);
    const int la_sel = lane >> 4;
    const int lb_row = ((lane >> 4) << 3) | (lane & 7);
    const int lb_sel = (lane >> 3) & 1;

    // staging index patterns (per thread)
    const int hr = tid >> 3, hc = tid & 7;        // H: row step 32
    const long hbase = (long)b * C_ * (N_ / 8);   // uint4 units
    const long fbase = (long)b * N_ * 8;

    // ---- load G tile [128 rows x 128B], swizzled ----
#pragma unroll
    for (int i = 0; i < 4; i++) {
        int idx = tid + i * 256;
        int r = idx >> 3, c = idx & 7;
        uint4 v = gsplit[(long)(b * N_ + q0 + r) * 8 + c];
        *(uint4*)(smem + OFF_SG + r * 128 + (((c) ^ (r & 7)) << 4)) = v;
    }

    // ---- prologue: issue stage 0 ----
    {
        const int s = 0, t = 0;
#pragma unroll
        for (int i = 0; i < 2; i++) {
            int idx = tid + i * 256;
            int r = idx >> 3, c = idx & 7;
            cp16(sb + OFF_SF(s) + r * 128 + (((c) ^ (r & 7)) << 4),
                 fsplit + fbase + (long)(t * 64 + r) * 8 + c);
        }
#pragma unroll
        for (int i = 0; i < 8; i++) {
            int r = hr + i * 32;
            uint32_t doff = r * 128 + (((hc) ^ (r & 7)) << 4);
            long gi = hbase + (long)r * (N_ / 8) + t * 8 + hc;
            cp16(sb + OFF_HHI(s) + doff, hhi4 + gi);
            cp16(sb + OFF_HLO(s) + doff, hlo4 + gi);
        }
        CP_COMMIT();
    }

    float o[2][16][4];
#pragma unroll
    for (int mh = 0; mh < 2; mh++)
#pragma unroll
        for (int i = 0; i < 16; i++)
#pragma unroll
            for (int j = 0; j < 4; j++) o[mh][i][j] = 0.f;
    float lsum[2][2] = {{0.f, 0.f}, {0.f, 0.f}};

#pragma unroll 1
    for (int t = 0; t < NT_; t++) {
        const int s = t & 1;
        // issue next stage
        if (t + 1 < NT_) {
            const int sn = (t + 1) & 1;
#pragma unroll
            for (int i = 0; i < 2; i++) {
                int idx = tid + i * 256;
                int r = idx >> 3, c = idx & 7;
                cp16(sb + OFF_SF(sn) + r * 128 + (((c) ^ (r & 7)) << 4),
                     fsplit + fbase + (long)((t + 1) * 64 + r) * 8 + c);
            }
#pragma unroll
            for (int i = 0; i < 8; i++) {
                int r = hr + i * 32;
                uint32_t doff = r * 128 + (((hc) ^ (r & 7)) << 4);
                long gi = hbase + (long)r * (N_ / 8) + (t + 1) * 8 + hc;
                cp16(sb + OFF_HHI(sn) + doff, hhi4 + gi);
                cp16(sb + OFF_HLO(sn) + doff, hlo4 + gi);
            }
            CP_COMMIT();
            CP_WAIT(1);
        } else {
            CP_WAIT(0);
        }
        __syncthreads();

        // ---- MMA1 + softmax per m16 half ----
        uint32_t phi[2][16], plo[2][16];
#pragma unroll
        for (int mh = 0; mh < 2; mh++) {
            // G A-fragments for this half
            uint32_t gh[2][4], gl[2][4];
            {
                int row = wm * 32 + mh * 16 + la_row;
                uint32_t rowoff = sb + OFF_SG + row * 128;
#pragma unroll
                for (int kc = 0; kc < 2; kc++) {
                    ldsm4(gh[kc], rowoff + ((((2 * kc) + la_sel) ^ (row & 7)) << 4));
                    ldsm4(gl[kc], rowoff + ((((4 + 2 * kc) + la_sel) ^ (row & 7)) << 4));
                }
            }
            float sv[8][4];
#pragma unroll
            for (int i = 0; i < 8; i++)
#pragma unroll
                for (int j = 0; j < 4; j++) sv[i][j] = 0.f;

#pragma unroll
            for (int n16 = 0; n16 < 4; n16++) {
                int row = n16 * 16 + lb_row;
                uint32_t rowoff = sb + OFF_SF(s) + row * 128;
                uint32_t fh0[4], fh1[4], fl0[4], fl1[4];
                ldsm4(fh0, rowoff + (((0 + lb_sel) ^ (row & 7)) << 4));
                ldsm4(fh1, rowoff + (((2 + lb_sel) ^ (row & 7)) << 4));
                ldsm4(fl0, rowoff + (((4 + lb_sel) ^ (row & 7)) << 4));
                ldsm4(fl1, rowoff + (((6 + lb_sel) ^ (row & 7)) << 4));
#pragma unroll
                for (int j = 0; j < 2; j++) {
                    float* sd = sv[n16 * 2 + j];
                    mma_bf16(sd, gh[0], fh0[2 * j], fh0[2 * j + 1]);
                    mma_bf16(sd, gh[1], fh1[2 * j], fh1[2 * j + 1]);
                    mma_bf16(sd, gh[0], fl0[2 * j], fl0[2 * j + 1]);
                    mma_bf16(sd, gh[1], fl1[2 * j], fl1[2 * j + 1]);
                    mma_bf16(sd, gl[0], fh0[2 * j], fh0[2 * j + 1]);
                    mma_bf16(sd, gl[1], fh1[2 * j], fh1[2 * j + 1]);
                }
            }
            // exp + pack
#pragma unroll
            for (int kc = 0; kc < 4; kc++) {
#pragma unroll
                for (int half = 0; half < 2; half++) {
                    float* sd = sv[2 * kc + half];
                    float p0 = __expf(sd[0] - 40.f);
                    float p1 = __expf(sd[1] - 40.f);
                    float p2 = __expf(sd[2] - 40.f);
                    float p3 = __expf(sd[3] - 40.f);
                    lsum[mh][0] += p0 + p1;
                    lsum[mh][1] += p2 + p3;
                    __nv_bfloat162 h01 = __floats2bfloat162_rn(p0, p1);
                    __nv_bfloat162 h23 = __floats2bfloat162_rn(p2, p3);
                    float2 f01 = __bfloat1622float2(h01);
                    float2 f23 = __bfloat1622float2(h23);
                    __nv_bfloat162 q01 = __floats2bfloat162_rn(p0 - f01.x, p1 - f01.y);
                    __nv_bfloat162 q23 = __floats2bfloat162_rn(p2 - f23.x, p3 - f23.y);
                    phi[mh][kc * 4 + half * 2 + 0] = *(uint32_t*)&h01;
                    phi[mh][kc * 4 + half * 2 + 1] = *(uint32_t*)&h23;
                    plo[mh][kc * 4 + half * 2 + 0] = *(uint32_t*)&q01;
                    plo[mh][kc * 4 + half * 2 + 1] = *(uint32_t*)&q23;
                }
            }
        }

        // ---- MMA2: O[32x128] += Ph.Hh + Ph.Hl + Pl.Hh, B frags shared over mh ----
#pragma unroll
        for (int n16 = 0; n16 < 8; n16++) {
            int row = wn * 128 + n16 * 16 + lb_row;
            uint32_t rhioff = sb + OFF_HHI(s) + row * 128;
            uint32_t rlooff = sb + OFF_HLO(s) + row * 128;
#pragma unroll
            for (int kc = 0; kc < 4; kc++) {
                uint32_t bh[4], bl[4];
                uint32_t csel = (((2 * kc) + lb_sel) ^ (row & 7)) << 4;
                ldsm4(bh, rhioff + csel);
                ldsm4(bl, rlooff + csel);
#pragma unroll
                for (int mh = 0; mh < 2; mh++) {
#pragma unroll
                    for (int j = 0; j < 2; j++) {
                        float* od = o[mh][n16 * 2 + j];
                        mma_bf16(od, &phi[mh][kc * 4], bh[2 * j], bh[2 * j + 1]);
                        mma_bf16(od, &phi[mh][kc * 4], bl[2 * j], bl[2 * j + 1]);
                        mma_bf16(od, &plo[mh][kc * 4], bh[2 * j], bh[2 * j + 1]);
                    }
                }
            }
        }
        __syncthreads();
    }

    // ---- reduce l over the 4 lanes sharing a row ----
#pragma unroll
    for (int mh = 0; mh < 2; mh++)
#pragma unroll
        for (int hh = 0; hh < 2; hh++) {
            lsum[mh][hh] += __shfl_xor_sync(0xFFFFFFFFu, lsum[mh][hh], 1);
            lsum[mh][hh] += __shfl_xor_sync(0xFFFFFFFFu, lsum[mh][hh], 2);
        }
    const float gam = gamma[0];

    // ---- epilogue: y = gamma * O/l + x ----
#pragma unroll
    for (int mh = 0; mh < 2; mh++) {
        const float inv0 = 1.f / lsum[mh][0], inv1 = 1.f / lsum[mh][1];
        const long row0g = ((long)b * N_ + q0 + wm * 32 + mh * 16 + (lane >> 2)) * C_;
        const long row1g = row0g + 8 * C_;
#pragma unroll
        for (int n16 = 0; n16 < 8; n16++) {
#pragma unroll
            for (int j = 0; j < 2; j++) {
                const float* od = o[mh][n16 * 2 + j];
                int ch = wn * 128 + n16 * 16 + j * 8 + (lane & 3) * 2;
                float2 xv = *(const float2*)(x + row0g + ch);
                float2 yv;
                yv.x = fmaf(gam, od[0] * inv0, xv.x);
                yv.y = fmaf(gam, od[1] * inv0, xv.y);
                *(float2*)(y + row0g + ch) = yv;
                xv = *(const float2*)(x + row1g + ch);
                yv.x = fmaf(gam, od[2] * inv1, xv.x);
                yv.y = fmaf(gam, od[3] * inv1, xv.y);
                *(float2*)(y + row1g + ch) = yv;
            }
        }
    }
}

// ---------------------------------------------------------------------------
extern "C" void kernel_launch(void* const* d_in, const int* in_sizes, int n_in,
                              void* d_out, int out_size)
{
    const float* x     = (const float*)d_in[0];
    const float* Wf    = (const float*)d_in[1];
    const float* bf    = (const float*)d_in[2];
    const float* Wg    = (const float*)d_in[3];
    const float* bg    = (const float*)d_in[4];
    const float* Wh    = (const float*)d_in[5];
    const float* bh    = (const float*)d_in[6];
    const float* gamma = (const float*)d_in[7];
    float* y = (float*)d_out;

    float* hp;
    void *fs, *gs, *hthi, *htlo;
    cudaGetSymbolAddress((void**)&hp, g_h);
    cudaGetSymbolAddress(&fs, g_fs);
    cudaGetSymbolAddress(&gs, g_gs);
    cudaGetSymbolAddress(&hthi, g_ht_hi);
    cudaGetSymbolAddress(&htlo, g_ht_lo);

    const int M = B_ * N_;

    proj_gemm_split<<<dim3(1, M / 64), 256>>>(x, Wf, bf, (__nv_bfloat16*)fs, M, C_);
    proj_gemm_split<<<dim3(1, M / 64), 256>>>(x, Wg, bg, (__nv_bfloat16*)gs, M, C_);
    proj_gemm<<<dim3(C_ / 32, M / 64), 256>>>(x, Wh, bh, hp, M, C_, C_);
    transpose_split<<<dim3(N_ / 32, C_ / 32, B_), 256>>>(
        hp, (__nv_bfloat16*)hthi, (__nv_bfloat16*)htlo);

    cudaFuncSetAttribute(attn_mma, cudaFuncAttributeMaxDynamicSharedMemorySize, SMEM_TOTAL);
    attn_mma<<<dim3(N_ / 128, B_), 256, SMEM_TOTAL>>>(
        (const uint4*)fs, (const uint4*)gs, (const uint4*)hthi, (const uint4*)htlo,
        x, gamma, y);
}

// round 5
// speedup vs baseline: 26.2816x; 1.4346x over previous
#include <cuda_runtime.h>
#include <cuda_fp16.h>
#include <math_constants.h>
#include <cstdint>

#define B_  4
#define N_  4096
#define C_  256
#define CK_ 32
#define NT_ 64   // key tiles of 64

// ---------------------------------------------------------------------------
// Scratch (__device__ globals; allocation-free rule)
// ---------------------------------------------------------------------------
__device__ __align__(16) float g_h[B_ * N_ * C_];        // values fp32 [B,N,256]
__device__ uint4 g_fs[B_ * N_ * 8];                      // F split fp16 [B,N,(32hi|32lo)]
__device__ uint4 g_gs[B_ * N_ * 8];                      // G split fp16 [B,N,(32hi|32lo)]
__device__ uint4 g_ht[B_ * C_ * N_ / 8];                 // H^T fp16 [B,C,N]

// ---------------------------------------------------------------------------
// Helpers
// ---------------------------------------------------------------------------
__device__ __forceinline__ uint32_t smem_u32(const void* p) {
    uint32_t a;
    asm("{ .reg .u64 t; cvta.to.shared.u64 t, %1; cvt.u32.u64 %0, t; }" : "=r"(a) : "l"(p));
    return a;
}
__device__ __forceinline__ void ldsm4(uint32_t* r, uint32_t addr) {
    asm volatile("ldmatrix.sync.aligned.m8n8.x4.shared.b16 {%0,%1,%2,%3}, [%4];"
        : "=r"(r[0]), "=r"(r[1]), "=r"(r[2]), "=r"(r[3]) : "r"(addr));
}
__device__ __forceinline__ void mma_f16(float* d, const uint32_t* a, uint32_t b0, uint32_t b1) {
    asm volatile("mma.sync.aligned.m16n8k16.row.col.f32.f16.f16.f32 "
        "{%0,%1,%2,%3}, {%4,%5,%6,%7}, {%8,%9}, {%0,%1,%2,%3};"
        : "+f"(d[0]), "+f"(d[1]), "+f"(d[2]), "+f"(d[3])
        : "r"(a[0]), "r"(a[1]), "r"(a[2]), "r"(a[3]), "r"(b0), "r"(b1));
}
__device__ __forceinline__ void cp16(uint32_t dst, const void* src) {
    asm volatile("cp.async.cg.shared.global [%0], [%1], 16;" :: "r"(dst), "l"(src) : "memory");
}
#define CP_COMMIT()  asm volatile("cp.async.commit_group;" ::: "memory")
#define CP_WAIT(n)   asm volatile("cp.async.wait_group %0;" :: "n"(n) : "memory")

// ---------------------------------------------------------------------------
// Projection GEMM fp32 (for h): C[M,Nc] = A[M,K] @ W[K,Nc] + bias
// ---------------------------------------------------------------------------
__global__ __launch_bounds__(256) void proj_gemm(
    const float* __restrict__ A, const float* __restrict__ W,
    const float* __restrict__ bias, float* __restrict__ C,
    int M, int K, int Nc)
{
    __shared__ float sA[64 * 33];
    __shared__ float sW[32 * 33];
    const int tid = threadIdx.x, col = tid & 31, rg = tid >> 5;
    const int row0 = blockIdx.y * 64, col0 = blockIdx.x * 32;
    float acc[8];
#pragma unroll
    for (int i = 0; i < 8; i++) acc[i] = 0.f;
    for (int k0 = 0; k0 < K; k0 += 32) {
#pragma unroll
        for (int i = 0; i < 8; i++) {
            int idx = tid + i * 256;
            sA[(idx >> 5) * 33 + (idx & 31)] = A[(long)(row0 + (idx >> 5)) * K + k0 + (idx & 31)];
        }
#pragma unroll
        for (int i = 0; i < 4; i++) {
            int idx = tid + i * 256;
            sW[(idx >> 5) * 33 + (idx & 31)] = W[(long)(k0 + (idx >> 5)) * Nc + col0 + (idx & 31)];
        }
        __syncthreads();
#pragma unroll 8
        for (int kk = 0; kk < 32; kk++) {
            float w = sW[kk * 33 + col];
#pragma unroll
            for (int i = 0; i < 8; i++)
                acc[i] = fmaf(sA[(rg * 8 + i) * 33 + kk], w, acc[i]);
        }
        __syncthreads();
    }
    float bv = bias[col0 + col];
#pragma unroll
    for (int i = 0; i < 8; i++)
        C[(long)(row0 + rg * 8 + i) * Nc + col0 + col] = acc[i] + bv;
}

// ---------------------------------------------------------------------------
// Projection GEMM fp32 -> split fp16 hi/lo output [M][(32hi|32lo)] (for f, g)
// ---------------------------------------------------------------------------
__global__ __launch_bounds__(256) void proj_gemm_split(
    const float* __restrict__ A, const float* __restrict__ W,
    const float* __restrict__ bias, __half* __restrict__ out,
    int M, int K)
{
    __shared__ float sA[64 * 33];
    __shared__ float sW[32 * 33];
    const int tid = threadIdx.x, col = tid & 31, rg = tid >> 5;
    const int row0 = blockIdx.y * 64;
    float acc[8];
#pragma unroll
    for (int i = 0; i < 8; i++) acc[i] = 0.f;
    for (int k0 = 0; k0 < K; k0 += 32) {
#pragma unroll
        for (int i = 0; i < 8; i++) {
            int idx = tid + i * 256;
            sA[(idx >> 5) * 33 + (idx & 31)] = A[(long)(row0 + (idx >> 5)) * K + k0 + (idx & 31)];
        }
#pragma unroll
        for (int i = 0; i < 4; i++) {
            int idx = tid + i * 256;
            sW[(idx >> 5) * 33 + (idx & 31)] = W[(long)(k0 + (idx >> 5)) * 32 + (idx & 31)];
        }
        __syncthreads();
#pragma unroll 8
        for (int kk = 0; kk < 32; kk++) {
            float w = sW[kk * 33 + col];
#pragma unroll
            for (int i = 0; i < 8; i++)
                acc[i] = fmaf(sA[(rg * 8 + i) * 33 + kk], w, acc[i]);
        }
        __syncthreads();
    }
    float bv = bias[col];
#pragma unroll
    for (int i = 0; i < 8; i++) {
        float v = acc[i] + bv;
        __half hv = __float2half_rn(v);
        __half lv = __float2half_rn(v - __half2float(hv));
        long r = row0 + rg * 8 + i;
        out[r * 64 + col] = hv;
        out[r * 64 + 32 + col] = lv;
    }
}

// ---------------------------------------------------------------------------
// Transpose h [B,N,C] fp32 -> Ht fp16 [B,C,N]
// ---------------------------------------------------------------------------
__global__ __launch_bounds__(256) void transpose_h(
    const float* __restrict__ h, __half* __restrict__ ht)
{
    __shared__ float ts[32][33];
    const int b = blockIdx.z, n0 = blockIdx.x * 32, c0 = blockIdx.y * 32;
    const int tx = threadIdx.x & 31, ty = threadIdx.x >> 5;
#pragma unroll
    for (int i = 0; i < 4; i++)
        ts[ty + 8 * i][tx] = h[(long)b * N_ * C_ + (long)(n0 + ty + 8 * i) * C_ + c0 + tx];
    __syncthreads();
#pragma unroll
    for (int i = 0; i < 4; i++) {
        int cl = ty + 8 * i;
        ht[(long)b * C_ * N_ + (long)(c0 + cl) * N_ + n0 + tx] = __float2half_rn(ts[tx][cl]);
    }
}

// ---------------------------------------------------------------------------
// Attention: block = 128 q-rows x batch (grid 32x4 = 128 blocks, 1/SM).
// 8 warps: wm = wid&3 (32 q-rows as 2x m16), wn = wid>>2 (128 ch each).
// fp16: MMA1 3-term split; MMA2 single-term. FA2 per-tile running-max rescale.
// 3-stage cp.async pipeline (F 8KB + Ht 32KB per stage).
// ---------------------------------------------------------------------------
#define OFF_SG     0                       // 128 x 128B = 16 KB
#define STAGE_SZ   (8192 + 32768)          // F + Ht = 40 KB
#define OFF_SF(s)  (16384 + (s) * STAGE_SZ)
#define OFF_SH(s)  (16384 + (s) * STAGE_SZ + 8192)
#define SMEM_TOTAL (16384 + 3 * STAGE_SZ)  // 136 KB

__global__ __launch_bounds__(256, 1) void attn_mma(
    const uint4* __restrict__ fsplit, const uint4* __restrict__ gsplit,
    const uint4* __restrict__ ht4,
    const float* __restrict__ x, const float* __restrict__ gamma, float* __restrict__ y)
{
    extern __shared__ char smem[];
    const uint32_t sb = smem_u32(smem);
    const int tid = threadIdx.x, lane = tid & 31, wid = tid >> 5;
    const int wm = wid & 3, wn = wid >> 2;
    const int b = blockIdx.y, q0 = blockIdx.x * 128;

    const int la_row = (((lane >> 3) & 1) << 3) | (lane & 7);
    const int la_sel = lane >> 4;
    const int lb_row = ((lane >> 4) << 3) | (lane & 7);
    const int lb_sel = (lane >> 3) & 1;

    const int hr = tid >> 3, hc = tid & 7;        // H staging: 8 rows/thread, step 32
    const long hbase = (long)b * C_ * (N_ / 8);   // uint4 units
    const long fbase = (long)b * N_ * 8;

    // ---- load G tile [128 rows x 128B], swizzled ----
#pragma unroll
    for (int i = 0; i < 4; i++) {
        int idx = tid + i * 256;
        int r = idx >> 3, c = idx & 7;
        uint4 v = gsplit[(long)(b * N_ + q0 + r) * 8 + c];
        *(uint4*)(smem + OFF_SG + r * 128 + (((c) ^ (r & 7)) << 4)) = v;
    }

    // ---- prologue: issue stages 0 and 1 ----
#pragma unroll
    for (int t = 0; t < 2; t++) {
#pragma unroll
        for (int i = 0; i < 2; i++) {
            int idx = tid + i * 256;
            int r = idx >> 3, c = idx & 7;
            cp16(sb + OFF_SF(t) + r * 128 + (((c) ^ (r & 7)) << 4),
                 fsplit + fbase + (long)(t * 64 + r) * 8 + c);
        }
#pragma unroll
        for (int i = 0; i < 8; i++) {
            int r = hr + i * 32;
            cp16(sb + OFF_SH(t) + r * 128 + (((hc) ^ (r & 7)) << 4),
                 ht4 + hbase + (long)r * (N_ / 8) + t * 8 + hc);
        }
        CP_COMMIT();
    }

    float o[2][16][4];
#pragma unroll
    for (int mh = 0; mh < 2; mh++)
#pragma unroll
        for (int i = 0; i < 16; i++)
#pragma unroll
            for (int j = 0; j < 4; j++) o[mh][i][j] = 0.f;
    float lsum[2][2] = {{0.f, 0.f}, {0.f, 0.f}};
    float mrun[2][2] = {{-CUDART_INF_F, -CUDART_INF_F}, {-CUDART_INF_F, -CUDART_INF_F}};

#pragma unroll 1
    for (int t = 0; t < NT_; t++) {
        const int s = t % 3;
        CP_WAIT(1);
        __syncthreads();

        // ---- MMA1 + softmax per m16 half ----
        uint32_t phi[2][16];
#pragma unroll
        for (int mh = 0; mh < 2; mh++) {
            uint32_t gh[2][4], gl[2][4];
            {
                int row = wm * 32 + mh * 16 + la_row;
                uint32_t rowoff = sb + OFF_SG + row * 128;
#pragma unroll
                for (int kc = 0; kc < 2; kc++) {
                    ldsm4(gh[kc], rowoff + ((((2 * kc) + la_sel) ^ (row & 7)) << 4));
                    ldsm4(gl[kc], rowoff + ((((4 + 2 * kc) + la_sel) ^ (row & 7)) << 4));
                }
            }
            float sv[8][4];
#pragma unroll
            for (int i = 0; i < 8; i++)
#pragma unroll
                for (int j = 0; j < 4; j++) sv[i][j] = 0.f;

#pragma unroll
            for (int n16 = 0; n16 < 4; n16++) {
                int row = n16 * 16 + lb_row;
                uint32_t rowoff = sb + OFF_SF(s) + row * 128;
                uint32_t fh0[4], fh1[4], fl0[4], fl1[4];
                ldsm4(fh0, rowoff + (((0 + lb_sel) ^ (row & 7)) << 4));
                ldsm4(fh1, rowoff + (((2 + lb_sel) ^ (row & 7)) << 4));
                ldsm4(fl0, rowoff + (((4 + lb_sel) ^ (row & 7)) << 4));
                ldsm4(fl1, rowoff + (((6 + lb_sel) ^ (row & 7)) << 4));
#pragma unroll
                for (int j = 0; j < 2; j++) {
                    float* sd = sv[n16 * 2 + j];
                    mma_f16(sd, gh[0], fh0[2 * j], fh0[2 * j + 1]);
                    mma_f16(sd, gh[1], fh1[2 * j], fh1[2 * j + 1]);
                    mma_f16(sd, gh[0], fl0[2 * j], fl0[2 * j + 1]);
                    mma_f16(sd, gh[1], fl1[2 * j], fl1[2 * j + 1]);
                    mma_f16(sd, gl[0], fh0[2 * j], fh0[2 * j + 1]);
                    mma_f16(sd, gl[1], fh1[2 * j], fh1[2 * j + 1]);
                }
            }

            // ---- per-tile row max over 64 keys (reduce across 4 lanes) ----
            float mt0 = -CUDART_INF_F, mt1 = -CUDART_INF_F;
#pragma unroll
            for (int i = 0; i < 8; i++) {
                mt0 = fmaxf(mt0, fmaxf(sv[i][0], sv[i][1]));
                mt1 = fmaxf(mt1, fmaxf(sv[i][2], sv[i][3]));
            }
            mt0 = fmaxf(mt0, __shfl_xor_sync(0xFFFFFFFFu, mt0, 1));
            mt0 = fmaxf(mt0, __shfl_xor_sync(0xFFFFFFFFu, mt0, 2));
            mt1 = fmaxf(mt1, __shfl_xor_sync(0xFFFFFFFFu, mt1, 1));
            mt1 = fmaxf(mt1, __shfl_xor_sync(0xFFFFFFFFu, mt1, 2));

            const float mn0 = fmaxf(mrun[mh][0], mt0);
            const float mn1 = fmaxf(mrun[mh][1], mt1);
            const float a0 = __expf(mrun[mh][0] - mn0);   // 0 on first tile
            const float a1 = __expf(mrun[mh][1] - mn1);
            mrun[mh][0] = mn0; mrun[mh][1] = mn1;
            lsum[mh][0] *= a0; lsum[mh][1] *= a1;
            if (a0 != 1.f) {
#pragma unroll
                for (int i = 0; i < 16; i++) { o[mh][i][0] *= a0; o[mh][i][1] *= a0; }
            }
            if (a1 != 1.f) {
#pragma unroll
                for (int i = 0; i < 16; i++) { o[mh][i][2] *= a1; o[mh][i][3] *= a1; }
            }

            // ---- p = exp(s - m); pack fp16 A-frags ----
#pragma unroll
            for (int kc = 0; kc < 4; kc++) {
#pragma unroll
                for (int half = 0; half < 2; half++) {
                    float* sd = sv[2 * kc + half];
                    float p0 = __expf(sd[0] - mn0);
                    float p1 = __expf(sd[1] - mn0);
                    float p2 = __expf(sd[2] - mn1);
                    float p3 = __expf(sd[3] - mn1);
                    lsum[mh][0] += p0 + p1;
                    lsum[mh][1] += p2 + p3;
                    __half2 h01 = __floats2half2_rn(p0, p1);
                    __half2 h23 = __floats2half2_rn(p2, p3);
                    phi[mh][kc * 4 + half * 2 + 0] = *(uint32_t*)&h01;
                    phi[mh][kc * 4 + half * 2 + 1] = *(uint32_t*)&h23;
                }
            }
        }

        // ---- MMA2: O[32x128] += P.Ht  (single term, B frags shared over mh) ----
#pragma unroll
        for (int n16 = 0; n16 < 8; n16++) {
            int row = wn * 128 + n16 * 16 + lb_row;
            uint32_t rhoff = sb + OFF_SH(s) + row * 128;
#pragma unroll
            for (int kc = 0; kc < 4; kc++) {
                uint32_t bh[4];
                ldsm4(bh, rhoff + ((((2 * kc) + lb_sel) ^ (row & 7)) << 4));
#pragma unroll
                for (int mh = 0; mh < 2; mh++) {
#pragma unroll
                    for (int j = 0; j < 2; j++) {
                        mma_f16(o[mh][n16 * 2 + j], &phi[mh][kc * 4], bh[2 * j], bh[2 * j + 1]);
                    }
                }
            }
        }

        // ---- issue stage t+2 (overwrites stage (t-1)%3; all warps are past it) ----
        if (t + 2 < NT_) {
            const int sn = (t + 2) % 3;
#pragma unroll
            for (int i = 0; i < 2; i++) {
                int idx = tid + i * 256;
                int r = idx >> 3, c = idx & 7;
                cp16(sb + OFF_SF(sn) + r * 128 + (((c) ^ (r & 7)) << 4),
                     fsplit + fbase + (long)((t + 2) * 64 + r) * 8 + c);
            }
#pragma unroll
            for (int i = 0; i < 8; i++) {
                int r = hr + i * 32;
                cp16(sb + OFF_SH(sn) + r * 128 + (((hc) ^ (r & 7)) << 4),
                     ht4 + hbase + (long)r * (N_ / 8) + (t + 2) * 8 + hc);
            }
        }
        CP_COMMIT();
    }

    // ---- reduce l over the 4 lanes sharing a row (m already lane-uniform) ----
#pragma unroll
    for (int mh = 0; mh < 2; mh++)
#pragma unroll
        for (int hh = 0; hh < 2; hh++) {
            lsum[mh][hh] += __shfl_xor_sync(0xFFFFFFFFu, lsum[mh][hh], 1);
            lsum[mh][hh] += __shfl_xor_sync(0xFFFFFFFFu, lsum[mh][hh], 2);
        }
    const float gam = gamma[0];

    // ---- epilogue: y = gamma * O/l + x ----
#pragma unroll
    for (int mh = 0; mh < 2; mh++) {
        const float inv0 = 1.f / lsum[mh][0], inv1 = 1.f / lsum[mh][1];
        const long row0g = ((long)b * N_ + q0 + wm * 32 + mh * 16 + (lane >> 2)) * C_;
        const long row1g = row0g + 8 * C_;
#pragma unroll
        for (int n16 = 0; n16 < 8; n16++) {
#pragma unroll
            for (int j = 0; j < 2; j++) {
                const float* od = o[mh][n16 * 2 + j];
                int ch = wn * 128 + n16 * 16 + j * 8 + (lane & 3) * 2;
                float2 xv = *(const float2*)(x + row0g + ch);
                float2 yv;
                yv.x = fmaf(gam, od[0] * inv0, xv.x);
                yv.y = fmaf(gam, od[1] * inv0, xv.y);
                *(float2*)(y + row0g + ch) = yv;
                xv = *(const float2*)(x + row1g + ch);
                yv.x = fmaf(gam, od[2] * inv1, xv.x);
                yv.y = fmaf(gam, od[3] * inv1, xv.y);
                *(float2*)(y + row1g + ch) = yv;
            }
        }
    }
}

// ---------------------------------------------------------------------------
extern "C" void kernel_launch(void* const* d_in, const int* in_sizes, int n_in,
                              void* d_out, int out_size)
{
    const float* x     = (const float*)d_in[0];
    const float* Wf    = (const float*)d_in[1];
    const float* bf    = (const float*)d_in[2];
    const float* Wg    = (const float*)d_in[3];
    const float* bg    = (const float*)d_in[4];
    const float* Wh    = (const float*)d_in[5];
    const float* bh    = (const float*)d_in[6];
    const float* gamma = (const float*)d_in[7];
    float* y = (float*)d_out;

    float* hp;
    void *fs, *gs, *ht;
    cudaGetSymbolAddress((void**)&hp, g_h);
    cudaGetSymbolAddress(&fs, g_fs);
    cudaGetSymbolAddress(&gs, g_gs);
    cudaGetSymbolAddress(&ht, g_ht);

    const int M = B_ * N_;

    proj_gemm_split<<<dim3(1, M / 64), 256>>>(x, Wf, bf, (__half*)fs, M, C_);
    proj_gemm_split<<<dim3(1, M / 64), 256>>>(x, Wg, bg, (__half*)gs, M, C_);
    proj_gemm<<<dim3(C_ / 32, M / 64), 256>>>(x, Wh, bh, hp, M, C_, C_);
    transpose_h<<<dim3(N_ / 32, C_ / 32, B_), 256>>>(hp, (__half*)ht);

    cudaFuncSetAttribute(attn_mma, cudaFuncAttributeMaxDynamicSharedMemorySize, SMEM_TOTAL);
    attn_mma<<<dim3(N_ / 128, B_), 256, SMEM_TOTAL>>>(
        (const uint4*)fs, (const uint4*)gs, (const uint4*)ht, x, gamma, y);
}

// round 6
// speedup vs baseline: 37.1303x; 1.4128x over previous
#include <cuda_runtime.h>
#include <cuda_fp16.h>
#include <math_constants.h>
#include <cstdint>

#define B_  4
#define N_  4096
#define C_  256
#define NT_ 64   // key tiles of 64
#define NP_ 320  // packed projection cols: 32 f + 32 g + 256 h

// ---------------------------------------------------------------------------
// Scratch (__device__ globals; allocation-free rule)
// ---------------------------------------------------------------------------
__device__ uint4 g_xs[B_ * N_ * 64];          // x split fp16 [BN][256hi|256lo]
__device__ uint4 g_wt[NP_ * 64];              // W^T split fp16 [320][256hi|256lo]
__device__ float g_pb[NP_];                   // packed bias
__device__ uint4 g_h16[B_ * N_ * C_ / 8];     // h fp16 [B,N,256]
__device__ uint4 g_fs[B_ * N_ * 8];           // F split fp16 [B,N,(32hi|32lo)]
__device__ uint4 g_gs[B_ * N_ * 8];           // G split fp16 [B,N,(32hi|32lo)]
__device__ uint4 g_ht[B_ * C_ * N_ / 8];      // H^T fp16 [B,C,N]

// ---------------------------------------------------------------------------
// Helpers
// ---------------------------------------------------------------------------
__device__ __forceinline__ uint32_t smem_u32(const void* p) {
    uint32_t a;
    asm("{ .reg .u64 t; cvta.to.shared.u64 t, %1; cvt.u32.u64 %0, t; }" : "=r"(a) : "l"(p));
    return a;
}
__device__ __forceinline__ void ldsm4(uint32_t* r, uint32_t addr) {
    asm volatile("ldmatrix.sync.aligned.m8n8.x4.shared.b16 {%0,%1,%2,%3}, [%4];"
        : "=r"(r[0]), "=r"(r[1]), "=r"(r[2]), "=r"(r[3]) : "r"(addr));
}
__device__ __forceinline__ void mma_f16(float* d, const uint32_t* a, uint32_t b0, uint32_t b1) {
    asm volatile("mma.sync.aligned.m16n8k16.row.col.f32.f16.f16.f32 "
        "{%0,%1,%2,%3}, {%4,%5,%6,%7}, {%8,%9}, {%0,%1,%2,%3};"
        : "+f"(d[0]), "+f"(d[1]), "+f"(d[2]), "+f"(d[3])
        : "r"(a[0]), "r"(a[1]), "r"(a[2]), "r"(a[3]), "r"(b0), "r"(b1));
}
__device__ __forceinline__ void cp16(uint32_t dst, const void* src) {
    asm volatile("cp.async.cg.shared.global [%0], [%1], 16;" :: "r"(dst), "l"(src) : "memory");
}
#define CP_COMMIT()  asm volatile("cp.async.commit_group;" ::: "memory")
#define CP_WAIT(n)   asm volatile("cp.async.wait_group %0;" :: "n"(n) : "memory")

// ---------------------------------------------------------------------------
// prep_x: x fp32 [BN,256] -> xs fp16 [BN][256hi|256lo]
// ---------------------------------------------------------------------------
__global__ __launch_bounds__(256) void prep_x(const float* __restrict__ x, uint4* __restrict__ xs)
{
    int id = blockIdx.x * 256 + threadIdx.x;       // 8-float chunk id
    int r = id >> 5, c = id & 31;
    const float4* src = (const float4*)(x + (long)r * 256 + c * 8);
    float4 v0 = src[0], v1 = src[1];
    float vv[8] = {v0.x, v0.y, v0.z, v0.w, v1.x, v1.y, v1.z, v1.w};
    __half hv[8], lv[8];
#pragma unroll
    for (int i = 0; i < 8; i++) {
        hv[i] = __float2half_rn(vv[i]);
        lv[i] = __float2half_rn(vv[i] - __half2float(hv[i]));
    }
    xs[(long)r * 64 + c]      = *(uint4*)hv;
    xs[(long)r * 64 + 32 + c] = *(uint4*)lv;
}

// ---------------------------------------------------------------------------
// prep_w: pack [Wf|Wg|Wh]^T fp16 hi/lo [320][256hi|256lo] + bias [320]
// ---------------------------------------------------------------------------
__global__ __launch_bounds__(256) void prep_w(
    const float* __restrict__ Wf, const float* __restrict__ Wg, const float* __restrict__ Wh,
    const float* __restrict__ bf, const float* __restrict__ bg, const float* __restrict__ bh,
    __half* __restrict__ wt, float* __restrict__ pb)
{
    int n = blockIdx.x, k = threadIdx.x;
    float w = (n < 32) ? Wf[k * 32 + n] : (n < 64) ? Wg[k * 32 + (n - 32)] : Wh[k * 256 + (n - 64)];
    __half hv = __float2half_rn(w);
    __half lv = __float2half_rn(w - __half2float(hv));
    wt[(long)n * 512 + k] = hv;
    wt[(long)n * 512 + 256 + k] = lv;
    if (k == 0)
        pb[n] = (n < 32) ? bf[n] : (n < 64) ? bg[n - 32] : bh[n - 64];
}

// ---------------------------------------------------------------------------
// Fused projection GEMM (tensor cores, fp16 3-term hi/lo split):
// P[M=16384, 320] = x @ [Wf|Wg|Wh] + b.  Block 128x64, 8 warps (4m x 2n).
// Epilogue: cols 0-31 -> fs (hi/lo split), 32-63 -> gs, 64-319 -> h16 fp16.
// ---------------------------------------------------------------------------
#define PG_STAGE 49152                             // A 32K + B 16K
#define PG_SMEM  (2 * PG_STAGE + 256)

__global__ __launch_bounds__(256) void proj_mma(
    const uint4* __restrict__ xs, const uint4* __restrict__ wt,
    const float* __restrict__ pb,
    __half* __restrict__ fsh, __half* __restrict__ gsh, __half* __restrict__ h16)
{
    extern __shared__ char smem[];
    const uint32_t sb = smem_u32(smem);
    float* sbias = (float*)(smem + 2 * PG_STAGE);
    const int tid = threadIdx.x, lane = tid & 31, wid = tid >> 5;
    const int wm = wid & 3, wn = wid >> 2;
    const int n0 = blockIdx.x * 64, m0 = blockIdx.y * 128;

    const int la_row = (((lane >> 3) & 1) << 3) | (lane & 7);
    const int la_sel = lane >> 4;
    const int lb_row = ((lane >> 4) << 3) | (lane & 7);
    const int lb_sel = (lane >> 3) & 1;

    if (tid < 64) sbias[tid] = pb[n0 + tid];

    // staging patterns
    const int ar = tid >> 3, ac = tid & 7;   // A: rows 0..127 via ar + i*32? (see below)
    // A: 128 rows x 8 chunks x 2 parts; per thread 4 chunks per part
    // B: 64 rows x 8 chunks x 2 parts; per thread 2 chunks per part

    auto issue_stage = [&](int kt, int st) {
        uint32_t base = sb + st * PG_STAGE;
#pragma unroll
        for (int i = 0; i < 4; i++) {
            int idx = tid + i * 256;
            int r = idx >> 3, c = idx & 7;
            uint32_t sw = ((c ^ (r & 7)) << 4);
            cp16(base + r * 128 + sw,          xs + (long)(m0 + r) * 64 + kt * 8 + c);
            cp16(base + 16384 + r * 128 + sw,  xs + (long)(m0 + r) * 64 + 32 + kt * 8 + c);
        }
#pragma unroll
        for (int i = 0; i < 2; i++) {
            int idx = tid + i * 256;
            int r = idx >> 3, c = idx & 7;
            uint32_t sw = ((c ^ (r & 7)) << 4);
            cp16(base + 32768 + r * 128 + sw,        wt + (long)(n0 + r) * 64 + kt * 8 + c);
            cp16(base + 32768 + 8192 + r * 128 + sw, wt + (long)(n0 + r) * 64 + 32 + kt * 8 + c);
        }
        CP_COMMIT();
    };

    issue_stage(0, 0);

    float d[2][4][4];
#pragma unroll
    for (int mh = 0; mh < 2; mh++)
#pragma unroll
        for (int i = 0; i < 4; i++)
#pragma unroll
            for (int j = 0; j < 4; j++) d[mh][i][j] = 0.f;

#pragma unroll 1
    for (int kt = 0; kt < 4; kt++) {
        if (kt < 3) { issue_stage(kt + 1, (kt + 1) & 1); CP_WAIT(1); }
        else        { CP_WAIT(0); }
        __syncthreads();
        uint32_t buf = sb + (kt & 1) * PG_STAGE;

#pragma unroll
        for (int kc = 0; kc < 4; kc++) {
            uint32_t ah[2][4], al[2][4], bh[2][4], bl[2][4];
#pragma unroll
            for (int mh = 0; mh < 2; mh++) {
                int arow = wm * 32 + mh * 16 + la_row;
                uint32_t sw = (((2 * kc + la_sel) ^ (arow & 7)) << 4);
                ldsm4(ah[mh], buf + arow * 128 + sw);
                ldsm4(al[mh], buf + 16384 + arow * 128 + sw);
            }
#pragma unroll
            for (int n16 = 0; n16 < 2; n16++) {
                int brow = wn * 32 + n16 * 16 + lb_row;
                uint32_t sw = (((2 * kc + lb_sel) ^ (brow & 7)) << 4);
                ldsm4(bh[n16], buf + 32768 + brow * 128 + sw);
                ldsm4(bl[n16], buf + 32768 + 8192 + brow * 128 + sw);
            }
#pragma unroll
            for (int mh = 0; mh < 2; mh++)
#pragma unroll
                for (int n16 = 0; n16 < 2; n16++)
#pragma unroll
                    for (int j = 0; j < 2; j++) {
                        float* dd = d[mh][n16 * 2 + j];
                        mma_f16(dd, ah[mh], bh[n16][2 * j], bh[n16][2 * j + 1]);
                        mma_f16(dd, ah[mh], bl[n16][2 * j], bl[n16][2 * j + 1]);
                        mma_f16(dd, al[mh], bh[n16][2 * j], bh[n16][2 * j + 1]);
                    }
        }
        __syncthreads();
    }

    // ---- epilogue ----
#pragma unroll
    for (int mh = 0; mh < 2; mh++) {
        const long mrow0 = m0 + wm * 32 + mh * 16 + (lane >> 2);
        const long mrow1 = mrow0 + 8;
#pragma unroll
        for (int n16 = 0; n16 < 2; n16++)
#pragma unroll
            for (int j = 0; j < 2; j++) {
                const float* dd = d[mh][n16 * 2 + j];
                int col = wn * 32 + n16 * 16 + j * 8 + (lane & 3) * 2;
                float b0 = sbias[col], b1 = sbias[col + 1];
                float v00 = dd[0] + b0, v01 = dd[1] + b1;   // row mrow0
                float v10 = dd[2] + b0, v11 = dd[3] + b1;   // row mrow1
                if (blockIdx.x == 0) {
                    __half* dst = (col < 32) ? fsh : gsh;
                    int c = col & 31;
                    __half2 h0 = __floats2half2_rn(v00, v01);
                    float2 f0 = __half22float2(h0);
                    __half2 l0 = __floats2half2_rn(v00 - f0.x, v01 - f0.y);
                    *(__half2*)(dst + mrow0 * 64 + c) = h0;
                    *(__half2*)(dst + mrow0 * 64 + 32 + c) = l0;
                    __half2 h1 = __floats2half2_rn(v10, v11);
                    float2 f1 = __half22float2(h1);
                    __half2 l1 = __floats2half2_rn(v10 - f1.x, v11 - f1.y);
                    *(__half2*)(dst + mrow1 * 64 + c) = h1;
                    *(__half2*)(dst + mrow1 * 64 + 32 + c) = l1;
                } else {
                    int ch = n0 - 64 + col;
                    *(__half2*)(h16 + mrow0 * 256 + ch) = __floats2half2_rn(v00, v01);
                    *(__half2*)(h16 + mrow1 * 256 + ch) = __floats2half2_rn(v10, v11);
                }
            }
    }
}

// ---------------------------------------------------------------------------
// Transpose h fp16 [B,N,C] -> Ht fp16 [B,C,N]
// ---------------------------------------------------------------------------
__global__ __launch_bounds__(256) void transpose_h(
    const __half* __restrict__ h, __half* __restrict__ ht)
{
    __shared__ __half ts[32][34];
    const int b = blockIdx.z, n0 = blockIdx.x * 32, c0 = blockIdx.y * 32;
    const int tx = threadIdx.x & 31, ty = threadIdx.x >> 5;
#pragma unroll
    for (int i = 0; i < 4; i++)
        ts[ty + 8 * i][tx] = h[((long)b * N_ + n0 + ty + 8 * i) * C_ + c0 + tx];
    __syncthreads();
#pragma unroll
    for (int i = 0; i < 4; i++) {
        int cl = ty + 8 * i;
        ht[(long)b * C_ * N_ + (long)(c0 + cl) * N_ + n0 + tx] = ts[tx][cl];
    }
}

// ---------------------------------------------------------------------------
// Attention (unchanged from round 5): block = 128 q-rows x batch.
// fp16 MMA1 3-term / MMA2 1-term, FA2 running-max, 3-stage cp.async.
// ---------------------------------------------------------------------------
#define OFF_SG     0
#define STAGE_SZ   (8192 + 32768)
#define OFF_SF(s)  (16384 + (s) * STAGE_SZ)
#define OFF_SH(s)  (16384 + (s) * STAGE_SZ + 8192)
#define SMEM_TOTAL (16384 + 3 * STAGE_SZ)

__global__ __launch_bounds__(256, 1) void attn_mma(
    const uint4* __restrict__ fsplit, const uint4* __restrict__ gsplit,
    const uint4* __restrict__ ht4,
    const float* __restrict__ x, const float* __restrict__ gamma, float* __restrict__ y)
{
    extern __shared__ char smem[];
    const uint32_t sb = smem_u32(smem);
    const int tid = threadIdx.x, lane = tid & 31, wid = tid >> 5;
    const int wm = wid & 3, wn = wid >> 2;
    const int b = blockIdx.y, q0 = blockIdx.x * 128;

    const int la_row = (((lane >> 3) & 1) << 3) | (lane & 7);
    const int la_sel = lane >> 4;
    const int lb_row = ((lane >> 4) << 3) | (lane & 7);
    const int lb_sel = (lane >> 3) & 1;

    const int hr = tid >> 3, hc = tid & 7;
    const long hbase = (long)b * C_ * (N_ / 8);
    const long fbase = (long)b * N_ * 8;

#pragma unroll
    for (int i = 0; i < 4; i++) {
        int idx = tid + i * 256;
        int r = idx >> 3, c = idx & 7;
        uint4 v = gsplit[(long)(b * N_ + q0 + r) * 8 + c];
        *(uint4*)(smem + OFF_SG + r * 128 + (((c) ^ (r & 7)) << 4)) = v;
    }

#pragma unroll
    for (int t = 0; t < 2; t++) {
#pragma unroll
        for (int i = 0; i < 2; i++) {
            int idx = tid + i * 256;
            int r = idx >> 3, c = idx & 7;
            cp16(sb + OFF_SF(t) + r * 128 + (((c) ^ (r & 7)) << 4),
                 fsplit + fbase + (long)(t * 64 + r) * 8 + c);
        }
#pragma unroll
        for (int i = 0; i < 8; i++) {
            int r = hr + i * 32;
            cp16(sb + OFF_SH(t) + r * 128 + (((hc) ^ (r & 7)) << 4),
                 ht4 + hbase + (long)r * (N_ / 8) + t * 8 + hc);
        }
        CP_COMMIT();
    }

    float o[2][16][4];
#pragma unroll
    for (int mh = 0; mh < 2; mh++)
#pragma unroll
        for (int i = 0; i < 16; i++)
#pragma unroll
            for (int j = 0; j < 4; j++) o[mh][i][j] = 0.f;
    float lsum[2][2] = {{0.f, 0.f}, {0.f, 0.f}};
    float mrun[2][2] = {{-CUDART_INF_F, -CUDART_INF_F}, {-CUDART_INF_F, -CUDART_INF_F}};

#pragma unroll 1
    for (int t = 0; t < NT_; t++) {
        const int s = t % 3;
        CP_WAIT(1);
        __syncthreads();

        uint32_t phi[2][16];
#pragma unroll
        for (int mh = 0; mh < 2; mh++) {
            uint32_t gh[2][4], gl[2][4];
            {
                int row = wm * 32 + mh * 16 + la_row;
                uint32_t rowoff = sb + OFF_SG + row * 128;
#pragma unroll
                for (int kc = 0; kc < 2; kc++) {
                    ldsm4(gh[kc], rowoff + ((((2 * kc) + la_sel) ^ (row & 7)) << 4));
                    ldsm4(gl[kc], rowoff + ((((4 + 2 * kc) + la_sel) ^ (row & 7)) << 4));
                }
            }
            float sv[8][4];
#pragma unroll
            for (int i = 0; i < 8; i++)
#pragma unroll
                for (int j = 0; j < 4; j++) sv[i][j] = 0.f;

#pragma unroll
            for (int n16 = 0; n16 < 4; n16++) {
                int row = n16 * 16 + lb_row;
                uint32_t rowoff = sb + OFF_SF(s) + row * 128;
                uint32_t fh0[4], fh1[4], fl0[4], fl1[4];
                ldsm4(fh0, rowoff + (((0 + lb_sel) ^ (row & 7)) << 4));
                ldsm4(fh1, rowoff + (((2 + lb_sel) ^ (row & 7)) << 4));
                ldsm4(fl0, rowoff + (((4 + lb_sel) ^ (row & 7)) << 4));
                ldsm4(fl1, rowoff + (((6 + lb_sel) ^ (row & 7)) << 4));
#pragma unroll
                for (int j = 0; j < 2; j++) {
                    float* sd = sv[n16 * 2 + j];
                    mma_f16(sd, gh[0], fh0[2 * j], fh0[2 * j + 1]);
                    mma_f16(sd, gh[1], fh1[2 * j], fh1[2 * j + 1]);
                    mma_f16(sd, gh[0], fl0[2 * j], fl0[2 * j + 1]);
                    mma_f16(sd, gh[1], fl1[2 * j], fl1[2 * j + 1]);
                    mma_f16(sd, gl[0], fh0[2 * j], fh0[2 * j + 1]);
                    mma_f16(sd, gl[1], fh1[2 * j], fh1[2 * j + 1]);
                }
            }

            float mt0 = -CUDART_INF_F, mt1 = -CUDART_INF_F;
#pragma unroll
            for (int i = 0; i < 8; i++) {
                mt0 = fmaxf(mt0, fmaxf(sv[i][0], sv[i][1]));
                mt1 = fmaxf(mt1, fmaxf(sv[i][2], sv[i][3]));
            }
            mt0 = fmaxf(mt0, __shfl_xor_sync(0xFFFFFFFFu, mt0, 1));
            mt0 = fmaxf(mt0, __shfl_xor_sync(0xFFFFFFFFu, mt0, 2));
            mt1 = fmaxf(mt1, __shfl_xor_sync(0xFFFFFFFFu, mt1, 1));
            mt1 = fmaxf(mt1, __shfl_xor_sync(0xFFFFFFFFu, mt1, 2));

            const float mn0 = fmaxf(mrun[mh][0], mt0);
            const float mn1 = fmaxf(mrun[mh][1], mt1);
            const float a0 = __expf(mrun[mh][0] - mn0);
            const float a1 = __expf(mrun[mh][1] - mn1);
            mrun[mh][0] = mn0; mrun[mh][1] = mn1;
            lsum[mh][0] *= a0; lsum[mh][1] *= a1;
            if (a0 != 1.f) {
#pragma unroll
                for (int i = 0; i < 16; i++) { o[mh][i][0] *= a0; o[mh][i][1] *= a0; }
            }
            if (a1 != 1.f) {
#pragma unroll
                for (int i = 0; i < 16; i++) { o[mh][i][2] *= a1; o[mh][i][3] *= a1; }
            }

#pragma unroll
            for (int kc = 0; kc < 4; kc++) {
#pragma unroll
                for (int half = 0; half < 2; half++) {
                    float* sd = sv[2 * kc + half];
                    float p0 = __expf(sd[0] - mn0);
                    float p1 = __expf(sd[1] - mn0);
                    float p2 = __expf(sd[2] - mn1);
                    float p3 = __expf(sd[3] - mn1);
                    lsum[mh][0] += p0 + p1;
                    lsum[mh][1] += p2 + p3;
                    __half2 h01 = __floats2half2_rn(p0, p1);
                    __half2 h23 = __floats2half2_rn(p2, p3);
                    phi[mh][kc * 4 + half * 2 + 0] = *(uint32_t*)&h01;
                    phi[mh][kc * 4 + half * 2 + 1] = *(uint32_t*)&h23;
                }
            }
        }

#pragma unroll
        for (int n16 = 0; n16 < 8; n16++) {
            int row = wn * 128 + n16 * 16 + lb_row;
            uint32_t rhoff = sb + OFF_SH(s) + row * 128;
#pragma unroll
            for (int kc = 0; kc < 4; kc++) {
                uint32_t bh[4];
                ldsm4(bh, rhoff + ((((2 * kc) + lb_sel) ^ (row & 7)) << 4));
#pragma unroll
                for (int mh = 0; mh < 2; mh++) {
#pragma unroll
                    for (int j = 0; j < 2; j++) {
                        mma_f16(o[mh][n16 * 2 + j], &phi[mh][kc * 4], bh[2 * j], bh[2 * j + 1]);
                    }
                }
            }
        }

        if (t + 2 < NT_) {
            const int sn = (t + 2) % 3;
#pragma unroll
            for (int i = 0; i < 2; i++) {
                int idx = tid + i * 256;
                int r = idx >> 3, c = idx & 7;
                cp16(sb + OFF_SF(sn) + r * 128 + (((c) ^ (r & 7)) << 4),
                     fsplit + fbase + (long)((t + 2) * 64 + r) * 8 + c);
            }
#pragma unroll
            for (int i = 0; i < 8; i++) {
                int r = hr + i * 32;
                cp16(sb + OFF_SH(sn) + r * 128 + (((hc) ^ (r & 7)) << 4),
                     ht4 + hbase + (long)r * (N_ / 8) + (t + 2) * 8 + hc);
            }
        }
        CP_COMMIT();
    }

#pragma unroll
    for (int mh = 0; mh < 2; mh++)
#pragma unroll
        for (int hh = 0; hh < 2; hh++) {
            lsum[mh][hh] += __shfl_xor_sync(0xFFFFFFFFu, lsum[mh][hh], 1);
            lsum[mh][hh] += __shfl_xor_sync(0xFFFFFFFFu, lsum[mh][hh], 2);
        }
    const float gam = gamma[0];

#pragma unroll
    for (int mh = 0; mh < 2; mh++) {
        const float inv0 = 1.f / lsum[mh][0], inv1 = 1.f / lsum[mh][1];
        const long row0g = ((long)b * N_ + q0 + wm * 32 + mh * 16 + (lane >> 2)) * C_;
        const long row1g = row0g + 8 * C_;
#pragma unroll
        for (int n16 = 0; n16 < 8; n16++) {
#pragma unroll
            for (int j = 0; j < 2; j++) {
                const float* od = o[mh][n16 * 2 + j];
                int ch = wn * 128 + n16 * 16 + j * 8 + (lane & 3) * 2;
                float2 xv = *(const float2*)(x + row0g + ch);
                float2 yv;
                yv.x = fmaf(gam, od[0] * inv0, xv.x);
                yv.y = fmaf(gam, od[1] * inv0, xv.y);
                *(float2*)(y + row0g + ch) = yv;
                xv = *(const float2*)(x + row1g + ch);
                yv.x = fmaf(gam, od[2] * inv1, xv.x);
                yv.y = fmaf(gam, od[3] * inv1, xv.y);
                *(float2*)(y + row1g + ch) = yv;
            }
        }
    }
}

// ---------------------------------------------------------------------------
extern "C" void kernel_launch(void* const* d_in, const int* in_sizes, int n_in,
                              void* d_out, int out_size)
{
    const float* x     = (const float*)d_in[0];
    const float* Wf    = (const float*)d_in[1];
    const float* bf    = (const float*)d_in[2];
    const float* Wg    = (const float*)d_in[3];
    const float* bg    = (const float*)d_in[4];
    const float* Wh    = (const float*)d_in[5];
    const float* bh    = (const float*)d_in[6];
    const float* gamma = (const float*)d_in[7];
    float* y = (float*)d_out;

    void *xs, *wt, *pb, *h16, *fs, *gs, *ht;
    cudaGetSymbolAddress(&xs, g_xs);
    cudaGetSymbolAddress(&wt, g_wt);
    cudaGetSymbolAddress(&pb, g_pb);
    cudaGetSymbolAddress(&h16, g_h16);
    cudaGetSymbolAddress(&fs, g_fs);
    cudaGetSymbolAddress(&gs, g_gs);
    cudaGetSymbolAddress(&ht, g_ht);

    const int M = B_ * N_;

    prep_x<<<M * 32 / 256, 256>>>(x, (uint4*)xs);
    prep_w<<<NP_, 256>>>(Wf, Wg, Wh, bf, bg, bh, (__half*)wt, (float*)pb);

    cudaFuncSetAttribute(proj_mma, cudaFuncAttributeMaxDynamicSharedMemorySize, PG_SMEM);
    proj_mma<<<dim3(NP_ / 64, M / 128), 256, PG_SMEM>>>(
        (const uint4*)xs, (const uint4*)wt, (const float*)pb,
        (__half*)fs, (__half*)gs, (__half*)h16);

    transpose_h<<<dim3(N_ / 32, C_ / 32, B_), 256>>>((const __half*)h16, (__half*)ht);

    cudaFuncSetAttribute(attn_mma, cudaFuncAttributeMaxDynamicSharedMemorySize, SMEM_TOTAL);
    attn_mma<<<dim3(N_ / 128, B_), 256, SMEM_TOTAL>>>(
        (const uint4*)fs, (const uint4*)gs, (const uint4*)ht, x, gamma, y);
}

// round 7
// speedup vs baseline: 49.5270x; 1.3339x over previous
#include <cuda_runtime.h>
#include <cuda_fp16.h>
#include <math_constants.h>
#include <cstdint>

#define B_  4
#define N_  4096
#define C_  256
#define NT_ 64   // key tiles of 64
#define NP_ 320  // packed projection cols: 32 f + 32 g + 256 h

// ---------------------------------------------------------------------------
// Scratch (__device__ globals; allocation-free rule)
// ---------------------------------------------------------------------------
__device__ uint4 g_xs[B_ * N_ * 64];          // x split fp16 [BN][256hi|256lo]
__device__ uint4 g_wt[NP_ * 64];              // W^T split fp16 [320][256hi|256lo]
__device__ float g_pb[NP_];                   // packed bias
__device__ uint4 g_h16[B_ * N_ * C_ / 8];     // h fp16 [B,N,256]
__device__ uint4 g_fs[B_ * N_ * 8];           // F split fp16 [B,N,(32hi|32lo)]
__device__ uint4 g_gs[B_ * N_ * 8];           // G split fp16 [B,N,(32hi|32lo)]
__device__ uint4 g_ht[B_ * C_ * N_ / 8];      // H^T fp16 [B,C,N]

// ---------------------------------------------------------------------------
// Helpers
// ---------------------------------------------------------------------------
__device__ __forceinline__ uint32_t smem_u32(const void* p) {
    uint32_t a;
    asm("{ .reg .u64 t; cvta.to.shared.u64 t, %1; cvt.u32.u64 %0, t; }" : "=r"(a) : "l"(p));
    return a;
}
__device__ __forceinline__ void ldsm4(uint32_t* r, uint32_t addr) {
    asm volatile("ldmatrix.sync.aligned.m8n8.x4.shared.b16 {%0,%1,%2,%3}, [%4];"
        : "=r"(r[0]), "=r"(r[1]), "=r"(r[2]), "=r"(r[3]) : "r"(addr));
}
__device__ __forceinline__ void mma_f16(float* d, const uint32_t* a, uint32_t b0, uint32_t b1) {
    asm volatile("mma.sync.aligned.m16n8k16.row.col.f32.f16.f16.f32 "
        "{%0,%1,%2,%3}, {%4,%5,%6,%7}, {%8,%9}, {%0,%1,%2,%3};"
        : "+f"(d[0]), "+f"(d[1]), "+f"(d[2]), "+f"(d[3])
        : "r"(a[0]), "r"(a[1]), "r"(a[2]), "r"(a[3]), "r"(b0), "r"(b1));
}
__device__ __forceinline__ void cp16(uint32_t dst, const void* src) {
    asm volatile("cp.async.cg.shared.global [%0], [%1], 16;" :: "r"(dst), "l"(src) : "memory");
}
#define CP_COMMIT()  asm volatile("cp.async.commit_group;" ::: "memory")
#define CP_WAIT(n)   asm volatile("cp.async.wait_group %0;" :: "n"(n) : "memory")

// ---------------------------------------------------------------------------
// prep_x: x fp32 [BN,256] -> xs fp16 [BN][256hi|256lo]
// ---------------------------------------------------------------------------
__global__ __launch_bounds__(256) void prep_x(const float* __restrict__ x, uint4* __restrict__ xs)
{
    int id = blockIdx.x * 256 + threadIdx.x;
    int r = id >> 5, c = id & 31;
    const float4* src = (const float4*)(x + (long)r * 256 + c * 8);
    float4 v0 = src[0], v1 = src[1];
    float vv[8] = {v0.x, v0.y, v0.z, v0.w, v1.x, v1.y, v1.z, v1.w};
    __half hv[8], lv[8];
#pragma unroll
    for (int i = 0; i < 8; i++) {
        hv[i] = __float2half_rn(vv[i]);
        lv[i] = __float2half_rn(vv[i] - __half2float(hv[i]));
    }
    xs[(long)r * 64 + c]      = *(uint4*)hv;
    xs[(long)r * 64 + 32 + c] = *(uint4*)lv;
}

// ---------------------------------------------------------------------------
// prep_w: pack [Wf|Wg|Wh]^T fp16 hi/lo [320][256hi|256lo] + bias [320]
// ---------------------------------------------------------------------------
__global__ __launch_bounds__(256) void prep_w(
    const float* __restrict__ Wf, const float* __restrict__ Wg, const float* __restrict__ Wh,
    const float* __restrict__ bf, const float* __restrict__ bg, const float* __restrict__ bh,
    __half* __restrict__ wt, float* __restrict__ pb)
{
    int n = blockIdx.x, k = threadIdx.x;
    float w = (n < 32) ? Wf[k * 32 + n] : (n < 64) ? Wg[k * 32 + (n - 32)] : Wh[k * 256 + (n - 64)];
    __half hv = __float2half_rn(w);
    __half lv = __float2half_rn(w - __half2float(hv));
    wt[(long)n * 512 + k] = hv;
    wt[(long)n * 512 + 256 + k] = lv;
    if (k == 0)
        pb[n] = (n < 32) ? bf[n] : (n < 64) ? bg[n - 32] : bh[n - 64];
}

// ---------------------------------------------------------------------------
// Fused projection GEMM (tensor cores, fp16 3-term hi/lo split)
// ---------------------------------------------------------------------------
#define PG_STAGE 49152
#define PG_SMEM  (2 * PG_STAGE + 256)

__global__ __launch_bounds__(256) void proj_mma(
    const uint4* __restrict__ xs, const uint4* __restrict__ wt,
    const float* __restrict__ pb,
    __half* __restrict__ fsh, __half* __restrict__ gsh, __half* __restrict__ h16)
{
    extern __shared__ char smem[];
    const uint32_t sb = smem_u32(smem);
    float* sbias = (float*)(smem + 2 * PG_STAGE);
    const int tid = threadIdx.x, lane = tid & 31, wid = tid >> 5;
    const int wm = wid & 3, wn = wid >> 2;
    const int n0 = blockIdx.x * 64, m0 = blockIdx.y * 128;

    const int la_row = (((lane >> 3) & 1) << 3) | (lane & 7);
    const int la_sel = lane >> 4;
    const int lb_row = ((lane >> 4) << 3) | (lane & 7);
    const int lb_sel = (lane >> 3) & 1;

    if (tid < 64) sbias[tid] = pb[n0 + tid];

    auto issue_stage = [&](int kt, int st) {
        uint32_t base = sb + st * PG_STAGE;
#pragma unroll
        for (int i = 0; i < 4; i++) {
            int idx = tid + i * 256;
            int r = idx >> 3, c = idx & 7;
            uint32_t sw = ((c ^ (r & 7)) << 4);
            cp16(base + r * 128 + sw,          xs + (long)(m0 + r) * 64 + kt * 8 + c);
            cp16(base + 16384 + r * 128 + sw,  xs + (long)(m0 + r) * 64 + 32 + kt * 8 + c);
        }
#pragma unroll
        for (int i = 0; i < 2; i++) {
            int idx = tid + i * 256;
            int r = idx >> 3, c = idx & 7;
            uint32_t sw = ((c ^ (r & 7)) << 4);
            cp16(base + 32768 + r * 128 + sw,        wt + (long)(n0 + r) * 64 + kt * 8 + c);
            cp16(base + 32768 + 8192 + r * 128 + sw, wt + (long)(n0 + r) * 64 + 32 + kt * 8 + c);
        }
        CP_COMMIT();
    };

    issue_stage(0, 0);

    float d[2][4][4];
#pragma unroll
    for (int mh = 0; mh < 2; mh++)
#pragma unroll
        for (int i = 0; i < 4; i++)
#pragma unroll
            for (int j = 0; j < 4; j++) d[mh][i][j] = 0.f;

#pragma unroll 1
    for (int kt = 0; kt < 4; kt++) {
        if (kt < 3) { issue_stage(kt + 1, (kt + 1) & 1); CP_WAIT(1); }
        else        { CP_WAIT(0); }
        __syncthreads();
        uint32_t buf = sb + (kt & 1) * PG_STAGE;

#pragma unroll
        for (int kc = 0; kc < 4; kc++) {
            uint32_t ah[2][4], al[2][4], bh[2][4], bl[2][4];
#pragma unroll
            for (int mh = 0; mh < 2; mh++) {
                int arow = wm * 32 + mh * 16 + la_row;
                uint32_t sw = (((2 * kc + la_sel) ^ (arow & 7)) << 4);
                ldsm4(ah[mh], buf + arow * 128 + sw);
                ldsm4(al[mh], buf + 16384 + arow * 128 + sw);
            }
#pragma unroll
            for (int n16 = 0; n16 < 2; n16++) {
                int brow = wn * 32 + n16 * 16 + lb_row;
                uint32_t sw = (((2 * kc + lb_sel) ^ (brow & 7)) << 4);
                ldsm4(bh[n16], buf + 32768 + brow * 128 + sw);
                ldsm4(bl[n16], buf + 32768 + 8192 + brow * 128 + sw);
            }
#pragma unroll
            for (int mh = 0; mh < 2; mh++)
#pragma unroll
                for (int n16 = 0; n16 < 2; n16++)
#pragma unroll
                    for (int j = 0; j < 2; j++) {
                        float* dd = d[mh][n16 * 2 + j];
                        mma_f16(dd, ah[mh], bh[n16][2 * j], bh[n16][2 * j + 1]);
                        mma_f16(dd, ah[mh], bl[n16][2 * j], bl[n16][2 * j + 1]);
                        mma_f16(dd, al[mh], bh[n16][2 * j], bh[n16][2 * j + 1]);
                    }
        }
        __syncthreads();
    }

#pragma unroll
    for (int mh = 0; mh < 2; mh++) {
        const long mrow0 = m0 + wm * 32 + mh * 16 + (lane >> 2);
        const long mrow1 = mrow0 + 8;
#pragma unroll
        for (int n16 = 0; n16 < 2; n16++)
#pragma unroll
            for (int j = 0; j < 2; j++) {
                const float* dd = d[mh][n16 * 2 + j];
                int col = wn * 32 + n16 * 16 + j * 8 + (lane & 3) * 2;
                float b0 = sbias[col], b1 = sbias[col + 1];
                float v00 = dd[0] + b0, v01 = dd[1] + b1;
                float v10 = dd[2] + b0, v11 = dd[3] + b1;
                if (blockIdx.x == 0) {
                    __half* dst = (col < 32) ? fsh : gsh;
                    int c = col & 31;
                    __half2 h0 = __floats2half2_rn(v00, v01);
                    float2 f0 = __half22float2(h0);
                    __half2 l0 = __floats2half2_rn(v00 - f0.x, v01 - f0.y);
                    *(__half2*)(dst + mrow0 * 64 + c) = h0;
                    *(__half2*)(dst + mrow0 * 64 + 32 + c) = l0;
                    __half2 h1 = __floats2half2_rn(v10, v11);
                    float2 f1 = __half22float2(h1);
                    __half2 l1 = __floats2half2_rn(v10 - f1.x, v11 - f1.y);
                    *(__half2*)(dst + mrow1 * 64 + c) = h1;
                    *(__half2*)(dst + mrow1 * 64 + 32 + c) = l1;
                } else {
                    int ch = n0 - 64 + col;
                    *(__half2*)(h16 + mrow0 * 256 + ch) = __floats2half2_rn(v00, v01);
                    *(__half2*)(h16 + mrow1 * 256 + ch) = __floats2half2_rn(v10, v11);
                }
            }
    }
}

// ---------------------------------------------------------------------------
// Transpose h fp16 [B,N,C] -> Ht fp16 [B,C,N]
// ---------------------------------------------------------------------------
__global__ __launch_bounds__(256) void transpose_h(
    const __half* __restrict__ h, __half* __restrict__ ht)
{
    __shared__ __half ts[32][34];
    const int b = blockIdx.z, n0 = blockIdx.x * 32, c0 = blockIdx.y * 32;
    const int tx = threadIdx.x & 31, ty = threadIdx.x >> 5;
#pragma unroll
    for (int i = 0; i < 4; i++)
        ts[ty + 8 * i][tx] = h[((long)b * N_ + n0 + ty + 8 * i) * C_ + c0 + tx];
    __syncthreads();
#pragma unroll
    for (int i = 0; i < 4; i++) {
        int cl = ty + 8 * i;
        ht[(long)b * C_ * N_ + (long)(c0 + cl) * N_ + n0 + tx] = ts[tx][cl];
    }
}

// ---------------------------------------------------------------------------
// Attention: block = 128 q-rows x batch. 8 warps, each owns ONE m16 row-slice
// (16 q-rows x 64 keys x 256 channels) — MMA1/exp computed exactly once,
// G fragments hoisted out of the tile loop.
// fp16 MMA1 3-term / MMA2 1-term, FA2 running-max, 3-stage cp.async.
// ---------------------------------------------------------------------------
#define OFF_SG     0
#define STAGE_SZ   (8192 + 32768)
#define OFF_SF(s)  (16384 + (s) * STAGE_SZ)
#define OFF_SH(s)  (16384 + (s) * STAGE_SZ + 8192)
#define SMEM_TOTAL (16384 + 3 * STAGE_SZ)

__global__ __launch_bounds__(256, 1) void attn_mma(
    const uint4* __restrict__ fsplit, const uint4* __restrict__ gsplit,
    const uint4* __restrict__ ht4,
    const float* __restrict__ x, const float* __restrict__ gamma, float* __restrict__ y)
{
    extern __shared__ char smem[];
    const uint32_t sb = smem_u32(smem);
    const int tid = threadIdx.x, lane = tid & 31, wid = tid >> 5;
    const int b = blockIdx.y, q0 = blockIdx.x * 128;

    const int la_row = (((lane >> 3) & 1) << 3) | (lane & 7);
    const int la_sel = lane >> 4;
    const int lb_row = ((lane >> 4) << 3) | (lane & 7);
    const int lb_sel = (lane >> 3) & 1;

    const int hr = tid >> 3, hc = tid & 7;
    const long hbase = (long)b * C_ * (N_ / 8);
    const long fbase = (long)b * N_ * 8;

    // ---- load G tile [128 rows x 128B], swizzled ----
#pragma unroll
    for (int i = 0; i < 4; i++) {
        int idx = tid + i * 256;
        int r = idx >> 3, c = idx & 7;
        uint4 v = gsplit[(long)(b * N_ + q0 + r) * 8 + c];
        *(uint4*)(smem + OFF_SG + r * 128 + (((c) ^ (r & 7)) << 4)) = v;
    }

    // ---- prologue: issue stages 0 and 1 ----
#pragma unroll
    for (int t = 0; t < 2; t++) {
#pragma unroll
        for (int i = 0; i < 2; i++) {
            int idx = tid + i * 256;
            int r = idx >> 3, c = idx & 7;
            cp16(sb + OFF_SF(t) + r * 128 + (((c) ^ (r & 7)) << 4),
                 fsplit + fbase + (long)(t * 64 + r) * 8 + c);
        }
#pragma unroll
        for (int i = 0; i < 8; i++) {
            int r = hr + i * 32;
            cp16(sb + OFF_SH(t) + r * 128 + (((hc) ^ (r & 7)) << 4),
                 ht4 + hbase + (long)r * (N_ / 8) + t * 8 + hc);
        }
        CP_COMMIT();
    }

    // ---- hoist G A-fragments for this warp's m16 (constant over tiles) ----
    __syncthreads();   // G smem writes complete
    uint32_t gh[2][4], gl[2][4];
    {
        int row = wid * 16 + la_row;
        uint32_t rowoff = sb + OFF_SG + row * 128;
#pragma unroll
        for (int kc = 0; kc < 2; kc++) {
            ldsm4(gh[kc], rowoff + ((((2 * kc) + la_sel) ^ (row & 7)) << 4));
            ldsm4(gl[kc], rowoff + ((((4 + 2 * kc) + la_sel) ^ (row & 7)) << 4));
        }
    }

    float o[32][4];
#pragma unroll
    for (int i = 0; i < 32; i++)
#pragma unroll
        for (int j = 0; j < 4; j++) o[i][j] = 0.f;
    float lsum0 = 0.f, lsum1 = 0.f;
    float mrun0 = -CUDART_INF_F, mrun1 = -CUDART_INF_F;

#pragma unroll 1
    for (int t = 0; t < NT_; t++) {
        const int s = t % 3;
        CP_WAIT(1);
        __syncthreads();

        // ---- MMA1: S[16x64], 3-term ----
        float sv[8][4];
#pragma unroll
        for (int i = 0; i < 8; i++)
#pragma unroll
            for (int j = 0; j < 4; j++) sv[i][j] = 0.f;

#pragma unroll
        for (int n16 = 0; n16 < 4; n16++) {
            int row = n16 * 16 + lb_row;
            uint32_t rowoff = sb + OFF_SF(s) + row * 128;
            uint32_t fh0[4], fh1[4], fl0[4], fl1[4];
            ldsm4(fh0, rowoff + (((0 + lb_sel) ^ (row & 7)) << 4));
            ldsm4(fh1, rowoff + (((2 + lb_sel) ^ (row & 7)) << 4));
            ldsm4(fl0, rowoff + (((4 + lb_sel) ^ (row & 7)) << 4));
            ldsm4(fl1, rowoff + (((6 + lb_sel) ^ (row & 7)) << 4));
#pragma unroll
            for (int j = 0; j < 2; j++) {
                float* sd = sv[n16 * 2 + j];
                mma_f16(sd, gh[0], fh0[2 * j], fh0[2 * j + 1]);
                mma_f16(sd, gh[1], fh1[2 * j], fh1[2 * j + 1]);
                mma_f16(sd, gh[0], fl0[2 * j], fl0[2 * j + 1]);
                mma_f16(sd, gh[1], fl1[2 * j], fl1[2 * j + 1]);
                mma_f16(sd, gl[0], fh0[2 * j], fh0[2 * j + 1]);
                mma_f16(sd, gl[1], fh1[2 * j], fh1[2 * j + 1]);
            }
        }

        // ---- per-tile row max (reduce across 4 lanes sharing each row) ----
        float mt0 = -CUDART_INF_F, mt1 = -CUDART_INF_F;
#pragma unroll
        for (int i = 0; i < 8; i++) {
            mt0 = fmaxf(mt0, fmaxf(sv[i][0], sv[i][1]));
            mt1 = fmaxf(mt1, fmaxf(sv[i][2], sv[i][3]));
        }
        mt0 = fmaxf(mt0, __shfl_xor_sync(0xFFFFFFFFu, mt0, 1));
        mt0 = fmaxf(mt0, __shfl_xor_sync(0xFFFFFFFFu, mt0, 2));
        mt1 = fmaxf(mt1, __shfl_xor_sync(0xFFFFFFFFu, mt1, 1));
        mt1 = fmaxf(mt1, __shfl_xor_sync(0xFFFFFFFFu, mt1, 2));

        const float mn0 = fmaxf(mrun0, mt0);
        const float mn1 = fmaxf(mrun1, mt1);
        const float a0 = __expf(mrun0 - mn0);
        const float a1 = __expf(mrun1 - mn1);
        mrun0 = mn0; mrun1 = mn1;
        lsum0 *= a0; lsum1 *= a1;
        if (a0 != 1.f) {
#pragma unroll
            for (int i = 0; i < 32; i++) { o[i][0] *= a0; o[i][1] *= a0; }
        }
        if (a1 != 1.f) {
#pragma unroll
            for (int i = 0; i < 32; i++) { o[i][2] *= a1; o[i][3] *= a1; }
        }

        // ---- p = exp(s - m); pack fp16 A-frags ----
        uint32_t phi[16];
#pragma unroll
        for (int kc = 0; kc < 4; kc++) {
#pragma unroll
            for (int half = 0; half < 2; half++) {
                float* sd = sv[2 * kc + half];
                float p0 = __expf(sd[0] - mn0);
                float p1 = __expf(sd[1] - mn0);
                float p2 = __expf(sd[2] - mn1);
                float p3 = __expf(sd[3] - mn1);
                lsum0 += p0 + p1;
                lsum1 += p2 + p3;
                __half2 h01 = __floats2half2_rn(p0, p1);
                __half2 h23 = __floats2half2_rn(p2, p3);
                phi[kc * 4 + half * 2 + 0] = *(uint32_t*)&h01;
                phi[kc * 4 + half * 2 + 1] = *(uint32_t*)&h23;
            }
        }

        // ---- MMA2: O[16x256] += P.Ht ----
#pragma unroll
        for (int n16 = 0; n16 < 16; n16++) {
            int row = n16 * 16 + lb_row;
            uint32_t rhoff = sb + OFF_SH(s) + row * 128;
#pragma unroll
            for (int kc = 0; kc < 4; kc++) {
                uint32_t bh[4];
                ldsm4(bh, rhoff + ((((2 * kc) + lb_sel) ^ (row & 7)) << 4));
#pragma unroll
                for (int j = 0; j < 2; j++) {
                    mma_f16(o[n16 * 2 + j], &phi[kc * 4], bh[2 * j], bh[2 * j + 1]);
                }
            }
        }

        // ---- issue stage t+2 ----
        if (t + 2 < NT_) {
            const int sn = (t + 2) % 3;
#pragma unroll
            for (int i = 0; i < 2; i++) {
                int idx = tid + i * 256;
                int r = idx >> 3, c = idx & 7;
                cp16(sb + OFF_SF(sn) + r * 128 + (((c) ^ (r & 7)) << 4),
                     fsplit + fbase + (long)((t + 2) * 64 + r) * 8 + c);
            }
#pragma unroll
            for (int i = 0; i < 8; i++) {
                int r = hr + i * 32;
                cp16(sb + OFF_SH(sn) + r * 128 + (((hc) ^ (r & 7)) << 4),
                     ht4 + hbase + (long)r * (N_ / 8) + (t + 2) * 8 + hc);
            }
        }
        CP_COMMIT();
    }

    // ---- reduce l over the 4 lanes sharing a row ----
    lsum0 += __shfl_xor_sync(0xFFFFFFFFu, lsum0, 1);
    lsum0 += __shfl_xor_sync(0xFFFFFFFFu, lsum0, 2);
    lsum1 += __shfl_xor_sync(0xFFFFFFFFu, lsum1, 1);
    lsum1 += __shfl_xor_sync(0xFFFFFFFFu, lsum1, 2);
    const float inv0 = 1.f / lsum0, inv1 = 1.f / lsum1;
    const float gam = gamma[0];

    // ---- epilogue: y = gamma * O/l + x ----
    const long row0g = ((long)b * N_ + q0 + wid * 16 + (lane >> 2)) * C_;
    const long row1g = row0g + 8 * C_;
#pragma unroll
    for (int n16 = 0; n16 < 16; n16++) {
#pragma unroll
        for (int j = 0; j < 2; j++) {
            const float* od = o[n16 * 2 + j];
            int ch = n16 * 16 + j * 8 + (lane & 3) * 2;
            float2 xv = *(const float2*)(x + row0g + ch);
            float2 yv;
            yv.x = fmaf(gam, od[0] * inv0, xv.x);
            yv.y = fmaf(gam, od[1] * inv0, xv.y);
            *(float2*)(y + row0g + ch) = yv;
            xv = *(const float2*)(x + row1g + ch);
            yv.x = fmaf(gam, od[2] * inv1, xv.x);
            yv.y = fmaf(gam, od[3] * inv1, xv.y);
            *(float2*)(y + row1g + ch) = yv;
        }
    }
}

// ---------------------------------------------------------------------------
extern "C" void kernel_launch(void* const* d_in, const int* in_sizes, int n_in,
                              void* d_out, int out_size)
{
    const float* x     = (const float*)d_in[0];
    const float* Wf    = (const float*)d_in[1];
    const float* bf    = (const float*)d_in[2];
    const float* Wg    = (const float*)d_in[3];
    const float* bg    = (const float*)d_in[4];
    const float* Wh    = (const float*)d_in[5];
    const float* bh    = (const float*)d_in[6];
    const float* gamma = (const float*)d_in[7];
    float* y = (float*)d_out;

    void *xs, *wt, *pb, *h16, *fs, *gs, *ht;
    cudaGetSymbolAddress(&xs, g_xs);
    cudaGetSymbolAddress(&wt, g_wt);
    cudaGetSymbolAddress(&pb, g_pb);
    cudaGetSymbolAddress(&h16, g_h16);
    cudaGetSymbolAddress(&fs, g_fs);
    cudaGetSymbolAddress(&gs, g_gs);
    cudaGetSymbolAddress(&ht, g_ht);

    const int M = B_ * N_;

    prep_x<<<M * 32 / 256, 256>>>(x, (uint4*)xs);
    prep_w<<<NP_, 256>>>(Wf, Wg, Wh, bf, bg, bh, (__half*)wt, (float*)pb);

    cudaFuncSetAttribute(proj_mma, cudaFuncAttributeMaxDynamicSharedMemorySize, PG_SMEM);
    proj_mma<<<dim3(NP_ / 64, M / 128), 256, PG_SMEM>>>(
        (const uint4*)xs, (const uint4*)wt, (const float*)pb,
        (__half*)fs, (__half*)gs, (__half*)h16);

    transpose_h<<<dim3(N_ / 32, C_ / 32, B_), 256>>>((const __half*)h16, (__half*)ht);

    cudaFuncSetAttribute(attn_mma, cudaFuncAttributeMaxDynamicSharedMemorySize, SMEM_TOTAL);
    attn_mma<<<dim3(N_ / 128, B_), 256, SMEM_TOTAL>>>(
        (const uint4*)fs, (const uint4*)gs, (const uint4*)ht, x, gamma, y);
}